// round 5
// baseline (speedup 1.0000x reference)
#include <cuda_runtime.h>
#include <cuda_bf16.h>
#include <cstdint>

#define NN 50000
#define NE 600000
#define DIM 128
#define NR 8
#define NB 8
#define NG 256
#define KA 256       // A2: [hi | lo]
#define KW 384       // W2: [Whi ; Whi ; Wlo]

// ---------------- static device scratch ----------------
__device__ __nv_bfloat16 g_A2[(size_t)NN * KA];              // split input, 25.6MB
__device__ __nv_bfloat16 g_W2[NR * DIM * KW];                // split transposed weights
__device__ float g_Hall[(size_t)NN * NR * DIM];              // 204.8 MB
__device__ float g_hA[(size_t)NN * DIM];
__device__ float g_hB[(size_t)NN * DIM];
__device__ float g_gate[NN];
__device__ float g_gmax[NG];
__device__ float g_gsum[NG];
__device__ float g_read[NG * DIM];

// ---------------- PTX helpers (Ampere-class ISA only) ----------------
__device__ __forceinline__ uint32_t smem_u32(const void* p) {
    uint32_t a;
    asm("{ .reg .u64 t; cvta.to.shared.u64 t, %1; cvt.u32.u64 %0, t; }" : "=r"(a) : "l"(p));
    return a;
}
#define CP_ASYNC16(dst, src) \
    asm volatile("cp.async.cg.shared.global [%0], [%1], 16;" :: "r"(dst), "l"(src))
#define CP_COMMIT() asm volatile("cp.async.commit_group;" ::: "memory")
#define CP_WAIT(n)  asm volatile("cp.async.wait_group %0;" :: "n"(n) : "memory")

#define LDMX4(f, addr) asm volatile( \
    "ldmatrix.sync.aligned.m8n8.x4.shared.b16 {%0,%1,%2,%3}, [%4];" \
    : "=r"((f)[0]), "=r"((f)[1]), "=r"((f)[2]), "=r"((f)[3]) : "r"(addr))

#define MMA_BF16(d, a, b0, b1) asm volatile( \
    "mma.sync.aligned.m16n8k16.row.col.f32.bf16.bf16.f32 " \
    "{%0,%1,%2,%3}, {%4,%5,%6,%7}, {%8,%9}, {%0,%1,%2,%3};" \
    : "+f"((d)[0]), "+f"((d)[1]), "+f"((d)[2]), "+f"((d)[3]) \
    : "r"((a)[0]), "r"((a)[1]), "r"((a)[2]), "r"((a)[3]), "r"(b0), "r"(b1))

// ---------------- split weights ----------------
__global__ void k_splitw(const float* __restrict__ bases, const float* __restrict__ comp) {
    int r = blockIdx.y;
    int t = blockIdx.x * 256 + threadIdx.x;
    if (t >= DIM * DIM) return;
    int k = t >> 7, n = t & 127;
    float s = 0.f;
#pragma unroll
    for (int b = 0; b < NB; b++)
        s = fmaf(comp[r * NB + b], bases[((size_t)b * DIM + k) * DIM + n], s);
    __nv_bfloat16 hi = __float2bfloat16(s);
    __nv_bfloat16 lo = __float2bfloat16(s - __bfloat162float(hi));
    __nv_bfloat16* w = g_W2 + ((size_t)r * DIM + n) * KW;
    w[k] = hi; w[128 + k] = hi; w[256 + k] = lo;
}

// ---------------- split activations: A2[n] = [hi | lo] ----------------
__global__ void k_split(const float* __restrict__ Aext, int whichA, int relu_in) {
    const float* __restrict__ A = (whichA == 0) ? Aext : (whichA == 1 ? g_hA : g_hB);
    size_t idx = (size_t)blockIdx.x * blockDim.x + threadIdx.x;   // NN*32
    if (idx >= (size_t)NN * 32) return;
    size_t n = idx >> 5;
    int c4 = (int)(idx & 31);
    float4 v = ((const float4*)(A + n * DIM))[c4];
    if (relu_in) {
        v.x = fmaxf(v.x, 0.f); v.y = fmaxf(v.y, 0.f);
        v.z = fmaxf(v.z, 0.f); v.w = fmaxf(v.w, 0.f);
    }
    __nv_bfloat16 h[4], l[4];
    float f[4] = {v.x, v.y, v.z, v.w};
#pragma unroll
    for (int i = 0; i < 4; i++) {
        h[i] = __float2bfloat16(f[i]);
        l[i] = __float2bfloat16(f[i] - __bfloat162float(h[i]));
    }
    __nv_bfloat16* a2 = g_A2 + n * KA + c4 * 4;
    *(uint2*)(a2)       = *(uint2*)h;
    *(uint2*)(a2 + 128) = *(uint2*)l;
}

// ---------------- HMMA GEMM, double-buffered BK=32 ----------------
// grid = (NR, 391): consecutive linear bids share the A tile -> L2 reuse.
__global__ __launch_bounds__(256) void k_gemm_mma() {
    constexpr int SP = 40;                                // bf16 per smem row (80B)
    __shared__ __nv_bfloat16 sA[2][128 * SP];
    __shared__ __nv_bfloat16 sB[2][128 * SP];

    const int tid = threadIdx.x;
    const int wid = tid >> 5, lane = tid & 31;
    const int r = blockIdx.x;
    const int m0 = blockIdx.y * 128;
    const int wm = (wid & 3) * 32;
    const int wn = (wid >> 2) * 64;

    const __nv_bfloat16* __restrict__ Ag = g_A2;
    const __nv_bfloat16* __restrict__ Bg = g_W2 + (size_t)r * DIM * KW;

    // A chunk offsets for the 12 W chunks: hi,hi,hi,hi, lo,lo,lo,lo, hi,hi,hi,hi
    const int a_off[12] = {0, 32, 64, 96, 128, 160, 192, 224, 0, 32, 64, 96};

    float acc[2][8][4];
#pragma unroll
    for (int mi = 0; mi < 2; mi++)
#pragma unroll
        for (int ni = 0; ni < 8; ni++)
#pragma unroll
            for (int q = 0; q < 4; q++) acc[mi][ni][q] = 0.f;

    const uint32_t sA_b0 = smem_u32(sA[0]), sB_b0 = smem_u32(sB[0]);
    const int lrow = (lane & 15);
    const int lcol = (lane & 16) ? 8 : 0;

    // per-thread staging coords: 512 x 16B per tile, 2 per thread per tile
    const int row_s = tid >> 1;                           // 0..127
    const int seg_s = (tid & 1) * 2;                      // 0 or 2  (two segs each)
    int grA = m0 + row_s; if (grA >= NN) grA = NN - 1;

    auto stage = [&](int c, int buf) {
        uint32_t sa = sA_b0 + buf * 128 * SP * 2;
        uint32_t sb = sB_b0 + buf * 128 * SP * 2;
        const __nv_bfloat16* arow = Ag + (size_t)grA * KA + a_off[c];
        const __nv_bfloat16* brow = Bg + (size_t)row_s * KW + c * 32;
#pragma unroll
        for (int s = 0; s < 2; s++) {
            CP_ASYNC16(sa + (row_s * SP + (seg_s + s) * 8) * 2, arow + (seg_s + s) * 8);
            CP_ASYNC16(sb + (row_s * SP + (seg_s + s) * 8) * 2, brow + (seg_s + s) * 8);
        }
    };

    stage(0, 0); CP_COMMIT();

    for (int c = 0; c < 12; c++) {
        if (c + 1 < 12) { stage(c + 1, (c + 1) & 1); CP_COMMIT(); CP_WAIT(1); }
        else { CP_WAIT(0); }
        __syncthreads();
        const uint32_t sa = sA_b0 + (c & 1) * 128 * SP * 2;
        const uint32_t sb = sB_b0 + (c & 1) * 128 * SP * 2;
#pragma unroll
        for (int ks = 0; ks < 2; ks++) {
            const int k0 = ks * 16;
            uint32_t aF[2][4], bF[4][4];
#pragma unroll
            for (int mi = 0; mi < 2; mi++)
                LDMX4(aF[mi], sa + ((wm + mi * 16 + lrow) * SP + k0 + lcol) * 2);
#pragma unroll
            for (int g = 0; g < 4; g++)
                LDMX4(bF[g], sb + ((wn + g * 16 + lrow) * SP + k0 + lcol) * 2);
#pragma unroll
            for (int mi = 0; mi < 2; mi++)
#pragma unroll
                for (int ni = 0; ni < 8; ni++) {
                    uint32_t b0 = bF[ni >> 1][(ni & 1)];
                    uint32_t b1 = bF[ni >> 1][(ni & 1) + 2];
                    MMA_BF16(acc[mi][ni], aF[mi], b0, b1);
                }
        }
        __syncthreads();
    }

    // epilogue
#pragma unroll
    for (int mi = 0; mi < 2; mi++) {
        int row0 = m0 + wm + mi * 16 + (lane >> 2);
#pragma unroll
        for (int half = 0; half < 2; half++) {
            int gr = row0 + half * 8;
            if (gr < NN) {
                float* base = g_Hall + ((size_t)gr * NR + r) * DIM + wn + (lane & 3) * 2;
#pragma unroll
                for (int ni = 0; ni < 8; ni++)
                    *(float2*)(base + ni * 8) =
                        make_float2(acc[mi][ni][half * 2], acc[mi][ni][half * 2 + 1]);
            }
        }
    }
}

// ---------------- out[n,:] = bias (vectorized) ----------------
__global__ void k_init(const float* __restrict__ bias, int whichOut) {
    float4* out = (float4*)((whichOut == 1) ? g_hA : g_hB);
    size_t idx = (size_t)blockIdx.x * blockDim.x + threadIdx.x;   // NN*32
    if (idx < (size_t)NN * 32)
        out[idx] = ((const float4*)bias)[idx & 31];
}

// ---------------- scatter: out[dst] += Hall[src, etype] ----------------
__global__ void k_scatter(const int* __restrict__ src, const int* __restrict__ dst,
                          const int* __restrict__ et, int whichOut) {
    float* out = (whichOut == 1) ? g_hA : g_hB;
    int e = blockIdx.x * 8 + (threadIdx.x >> 5);
    if (e >= NE) return;
    int lane = threadIdx.x & 31;
    int s = __ldg(src + e), d = __ldg(dst + e), r = __ldg(et + e);
    float4 v = ((const float4*)(g_Hall + ((size_t)s * NR + r) * DIM))[lane];
    float* o = out + (size_t)d * DIM + lane * 4;
    asm volatile("red.global.add.v4.f32 [%0], {%1,%2,%3,%4};"
                 :: "l"(o), "f"(v.x), "f"(v.y), "f"(v.z), "f"(v.w) : "memory");
}

// ---------------- pooling ----------------
__global__ void k_poolinit() {
    int idx = blockIdx.x * blockDim.x + threadIdx.x;
    if (idx < NG) { g_gmax[idx] = -__int_as_float(0x7f800000); g_gsum[idx] = 0.f; }
    if (idx < NG * DIM) g_read[idx] = 0.f;
}

__global__ void k_gate(const float* __restrict__ gw, const float* __restrict__ gb,
                       const int* __restrict__ n2g) {
    int n = blockIdx.x * 8 + (threadIdx.x >> 5);
    if (n >= NN) return;
    int lane = threadIdx.x & 31;
    float4 hv = ((const float4*)(g_hA + (size_t)n * DIM))[lane];
    float4 wv = ((const float4*)gw)[lane];
    float s = hv.x * wv.x + hv.y * wv.y + hv.z * wv.z + hv.w * wv.w;
#pragma unroll
    for (int o = 16; o; o >>= 1) s += __shfl_xor_sync(0xffffffffu, s, o);
    if (lane == 0) {
        s += gb[0];
        g_gate[n] = s;
        int g = n2g[n];
        int* ia = (int*)&g_gmax[g];
        int old = *ia;
        while (__int_as_float(old) < s) {
            int prev = atomicCAS(ia, old, __float_as_int(s));
            if (prev == old) break;
            old = prev;
        }
    }
}

__global__ void k_expsum(const int* __restrict__ n2g) {
    int n = blockIdx.x * blockDim.x + threadIdx.x;
    if (n >= NN) return;
    int g = n2g[n];
    float e = expf(g_gate[n] - g_gmax[g]);
    g_gate[n] = e;
    atomicAdd(&g_gsum[g], e);
}

__global__ void k_readout(const int* __restrict__ n2g) {
    int n = blockIdx.x * 8 + (threadIdx.x >> 5);
    if (n >= NN) return;
    int lane = threadIdx.x & 31;
    int g = n2g[n];
    float w = g_gate[n] / g_gsum[g];
    float4 hv = ((const float4*)(g_hA + (size_t)n * DIM))[lane];
    float* o = g_read + g * DIM + lane * 4;
    asm volatile("red.global.add.v4.f32 [%0], {%1,%2,%3,%4};"
                 :: "l"(o), "f"(hv.x * w), "f"(hv.y * w), "f"(hv.z * w), "f"(hv.w * w)
                 : "memory");
}

// ---------------- MLP head ----------------
__global__ void k_mlp(const float* __restrict__ fc1_w, const float* __restrict__ fc1_b,
                      const float* __restrict__ fc2_w, const float* __restrict__ fc2_b,
                      const float* __restrict__ fc3_w, const float* __restrict__ fc3_b,
                      float* __restrict__ out) {
    int g = blockIdx.x;
    int t = threadIdx.x;
    __shared__ float r[DIM];
    __shared__ float z1[100];
    __shared__ float z2[64];
    r[t] = g_read[g * DIM + t];
    __syncthreads();
    if (t < 100) {
        float s = fc1_b[t];
        for (int i = 0; i < DIM; i++) s = fmaf(r[i], fc1_w[i * 100 + t], s);
        z1[t] = fmaxf(s, 0.f);
    }
    __syncthreads();
    if (t < 64) {
        float s = fc2_b[t];
        for (int i = 0; i < 100; i++) s = fmaf(z1[i], fc2_w[i * 64 + t], s);
        z2[t] = fmaxf(s, 0.f);
    }
    __syncthreads();
    if (t == 0) {
        float s = fc3_b[0];
        for (int i = 0; i < 64; i++) s = fmaf(z2[i], fc3_w[i], s);
        out[g] = 1.f / (1.f + expf(-s));
    }
}

// ---------------- host launcher ----------------
extern "C" void kernel_launch(void* const* d_in, const int* in_sizes, int n_in,
                              void* d_out, int out_size) {
    const float *features, *bases1, *comp1, *bias1, *bases2, *comp2, *bias2;
    const float *bases3, *comp3, *bias3, *gate_w, *gate_b;
    const float *fc1_w, *fc1_b, *fc2_w, *fc2_b, *fc3_w, *fc3_b;
    const int *src, *dst, *etype, *n2g;

    if (in_sizes[1] == NE) {
        features = (const float*)d_in[0];
        src      = (const int*)d_in[1];
        dst      = (const int*)d_in[2];
        etype    = (const int*)d_in[3];
        n2g      = (const int*)d_in[4];
        bases1 = (const float*)d_in[5];  comp1 = (const float*)d_in[6];  bias1 = (const float*)d_in[7];
        bases2 = (const float*)d_in[8];  comp2 = (const float*)d_in[9];  bias2 = (const float*)d_in[10];
        bases3 = (const float*)d_in[11]; comp3 = (const float*)d_in[12]; bias3 = (const float*)d_in[13];
        gate_w = (const float*)d_in[14]; gate_b = (const float*)d_in[15];
        fc1_w = (const float*)d_in[16]; fc1_b = (const float*)d_in[17];
        fc2_w = (const float*)d_in[18]; fc2_b = (const float*)d_in[19];
        fc3_w = (const float*)d_in[20]; fc3_b = (const float*)d_in[21];
    } else {
        features = (const float*)d_in[0];
        bases1 = (const float*)d_in[1];  comp1 = (const float*)d_in[2];  bias1 = (const float*)d_in[3];
        bases2 = (const float*)d_in[4];  comp2 = (const float*)d_in[5];  bias2 = (const float*)d_in[6];
        bases3 = (const float*)d_in[7];  comp3 = (const float*)d_in[8];  bias3 = (const float*)d_in[9];
        gate_w = (const float*)d_in[10]; gate_b = (const float*)d_in[11];
        fc1_w = (const float*)d_in[12]; fc1_b = (const float*)d_in[13];
        fc2_w = (const float*)d_in[14]; fc2_b = (const float*)d_in[15];
        fc3_w = (const float*)d_in[16]; fc3_b = (const float*)d_in[17];
        src   = (const int*)d_in[18];
        dst   = (const int*)d_in[19];
        etype = (const int*)d_in[20];
        n2g   = (const int*)d_in[21];
    }
    float* out = (float*)d_out;

    const dim3 gemm_grid(NR, (NN + 127) / 128);          // 8 x 391, A-tile L2 reuse
    const dim3 splitw_grid(64, NR);
    const int split_blocks = (NN * 32 + 255) / 256;      // 6250
    const int scat_blocks = NE / 8;
    const int node_warp_blocks = NN / 8;

    // ---- layer 1: features -> g_hA
    k_splitw<<<splitw_grid, 256>>>(bases1, comp1);
    k_split<<<split_blocks, 256>>>(features, 0, 0);
    k_gemm_mma<<<gemm_grid, 256>>>();
    k_init<<<split_blocks, 256>>>(bias1, 1);
    k_scatter<<<scat_blocks, 256>>>(src, dst, etype, 1);
    // ---- layer 2: relu(g_hA) -> g_hB
    k_splitw<<<splitw_grid, 256>>>(bases2, comp2);
    k_split<<<split_blocks, 256>>>(features, 1, 1);
    k_gemm_mma<<<gemm_grid, 256>>>();
    k_init<<<split_blocks, 256>>>(bias2, 2);
    k_scatter<<<scat_blocks, 256>>>(src, dst, etype, 2);
    // ---- layer 3: relu(g_hB) -> g_hA
    k_splitw<<<splitw_grid, 256>>>(bases3, comp3);
    k_split<<<split_blocks, 256>>>(features, 2, 1);
    k_gemm_mma<<<gemm_grid, 256>>>();
    k_init<<<split_blocks, 256>>>(bias3, 1);
    k_scatter<<<scat_blocks, 256>>>(src, dst, etype, 1);
    // ---- attention pooling on g_hA
    k_poolinit<<<(NG * DIM + 255) / 256, 256>>>();
    k_gate<<<node_warp_blocks, 256>>>(gate_w, gate_b, n2g);
    k_expsum<<<(NN + 255) / 256, 256>>>(n2g);
    k_readout<<<node_warp_blocks, 256>>>(n2g);
    // ---- MLP head
    k_mlp<<<NG, DIM>>>(fc1_w, fc1_b, fc2_w, fc2_b, fc3_w, fc3_b, out);
}

// round 7
// speedup vs baseline: 1.1188x; 1.1188x over previous
#include <cuda_runtime.h>
#include <cuda_bf16.h>
#include <cstdint>

#define NN 50000
#define NE 600000
#define DIM 128
#define NR 8
#define NB 8
#define NG 256
#define KA 256       // A2: [hi | lo]
#define KW 384       // W2: [Whi ; Whi ; Wlo]

// ---------------- static device scratch ----------------
__device__ __nv_bfloat16 g_A2[(size_t)NN * KA];              // split input, 25.6MB
__device__ __nv_bfloat16 g_W2[NR * DIM * KW];                // split transposed weights
__device__ float g_Hall[(size_t)NN * NR * DIM];              // 204.8 MB fp32
__device__ float g_hA[(size_t)NN * DIM];
__device__ float g_hB[(size_t)NN * DIM];
__device__ float g_gate[NN];
__device__ float g_gmax[NG];
__device__ float g_gsum[NG];
__device__ float g_read[NG * DIM];

// ---------------- PTX helpers (Ampere-class ISA only) ----------------
__device__ __forceinline__ uint32_t smem_u32(const void* p) {
    uint32_t a;
    asm("{ .reg .u64 t; cvta.to.shared.u64 t, %1; cvt.u32.u64 %0, t; }" : "=r"(a) : "l"(p));
    return a;
}
#define CP_ASYNC16(dst, src) \
    asm volatile("cp.async.cg.shared.global [%0], [%1], 16;" :: "r"(dst), "l"(src))
#define CP_COMMIT() asm volatile("cp.async.commit_group;" ::: "memory")
#define CP_WAIT0()  asm volatile("cp.async.wait_group 0;" ::: "memory")

#define LDMX4(f, addr) asm volatile( \
    "ldmatrix.sync.aligned.m8n8.x4.shared.b16 {%0,%1,%2,%3}, [%4];" \
    : "=r"((f)[0]), "=r"((f)[1]), "=r"((f)[2]), "=r"((f)[3]) : "r"(addr))

#define MMA_BF16(d, a, b0, b1) asm volatile( \
    "mma.sync.aligned.m16n8k16.row.col.f32.bf16.bf16.f32 " \
    "{%0,%1,%2,%3}, {%4,%5,%6,%7}, {%8,%9}, {%0,%1,%2,%3};" \
    : "+f"((d)[0]), "+f"((d)[1]), "+f"((d)[2]), "+f"((d)[3]) \
    : "r"((a)[0]), "r"((a)[1]), "r"((a)[2]), "r"((a)[3]), "r"(b0), "r"(b1))

// ---------------- split weights ----------------
__global__ void k_splitw(const float* __restrict__ bases, const float* __restrict__ comp) {
    int r = blockIdx.y;
    int t = blockIdx.x * 256 + threadIdx.x;
    if (t >= DIM * DIM) return;
    int k = t >> 7, n = t & 127;
    float s = 0.f;
#pragma unroll
    for (int b = 0; b < NB; b++)
        s = fmaf(comp[r * NB + b], bases[((size_t)b * DIM + k) * DIM + n], s);
    __nv_bfloat16 hi = __float2bfloat16(s);
    __nv_bfloat16 lo = __float2bfloat16(s - __bfloat162float(hi));
    __nv_bfloat16* w = g_W2 + ((size_t)r * DIM + n) * KW;
    w[k] = hi; w[128 + k] = hi; w[256 + k] = lo;
}

// ---------------- split activations: A2[n] = [hi | lo] ----------------
__global__ void k_split(const float* __restrict__ Aext, int whichA, int relu_in) {
    const float* __restrict__ A = (whichA == 0) ? Aext : (whichA == 1 ? g_hA : g_hB);
    size_t idx = (size_t)blockIdx.x * blockDim.x + threadIdx.x;   // NN*32
    if (idx >= (size_t)NN * 32) return;
    size_t n = idx >> 5;
    int c4 = (int)(idx & 31);
    float4 v = ((const float4*)(A + n * DIM))[c4];
    if (relu_in) {
        v.x = fmaxf(v.x, 0.f); v.y = fmaxf(v.y, 0.f);
        v.z = fmaxf(v.z, 0.f); v.w = fmaxf(v.w, 0.f);
    }
    __nv_bfloat16 h[4], l[4];
    float f[4] = {v.x, v.y, v.z, v.w};
#pragma unroll
    for (int i = 0; i < 4; i++) {
        h[i] = __float2bfloat16(f[i]);
        l[i] = __float2bfloat16(f[i] - __bfloat162float(h[i]));
    }
    __nv_bfloat16* a2 = g_A2 + n * KA + c4 * 4;
    *(uint2*)(a2)       = *(uint2*)h;
    *(uint2*)(a2 + 128) = *(uint2*)l;
}

// ---------------- HMMA GEMM (R4 structure): BK=64, single stage, 2 CTA/SM ----------------
__global__ __launch_bounds__(256, 2) void k_gemm_mma() {
    constexpr int SP = 72;                                // bf16 per smem row
    __shared__ __nv_bfloat16 sA[128 * SP];
    __shared__ __nv_bfloat16 sB[128 * SP];

    const int tid = threadIdx.x;
    const int wid = tid >> 5, lane = tid & 31;
    const int r = blockIdx.y;
    const int m0 = blockIdx.x * 128;
    const int wm = (wid & 3) * 32;
    const int wn = (wid >> 2) * 64;

    const __nv_bfloat16* __restrict__ Ag = g_A2;
    const __nv_bfloat16* __restrict__ Bg = g_W2 + (size_t)r * DIM * KW;

    // A offsets in compact [hi|lo] for the 6 BK=64 W-chunks: hi hi lo lo hi hi
    const int a_off[6] = {0, 64, 128, 192, 0, 64};

    float acc[2][8][4];
#pragma unroll
    for (int mi = 0; mi < 2; mi++)
#pragma unroll
        for (int ni = 0; ni < 8; ni++)
#pragma unroll
            for (int q = 0; q < 4; q++) acc[mi][ni][q] = 0.f;

    const uint32_t sA_b = smem_u32(sA), sB_b = smem_u32(sB);
    const int lrow = (lane & 15);
    const int lcol = (lane & 16) ? 8 : 0;

    for (int kc = 0; kc < 6; kc++) {
        // stage chunk: 128 rows x 64 bf16 each for A and B (4 x 16B per thread each)
#pragma unroll
        for (int i = 0; i < 4; i++) {
            int id = tid + i * 256;
            int row = id >> 3, seg = id & 7;
            int gr = m0 + row; if (gr >= NN) gr = NN - 1;
            CP_ASYNC16(sA_b + (row * SP + seg * 8) * 2,
                       Ag + (size_t)gr * KA + a_off[kc] + seg * 8);
            CP_ASYNC16(sB_b + (row * SP + seg * 8) * 2,
                       Bg + (size_t)row * KW + kc * 64 + seg * 8);
        }
        CP_COMMIT(); CP_WAIT0();
        __syncthreads();

#pragma unroll
        for (int ks = 0; ks < 4; ks++) {
            const int k0 = ks * 16;
            uint32_t aF[2][4], bF[4][4];
#pragma unroll
            for (int mi = 0; mi < 2; mi++)
                LDMX4(aF[mi], sA_b + ((wm + mi * 16 + lrow) * SP + k0 + lcol) * 2);
#pragma unroll
            for (int g = 0; g < 4; g++)
                LDMX4(bF[g], sB_b + ((wn + g * 16 + lrow) * SP + k0 + lcol) * 2);
#pragma unroll
            for (int mi = 0; mi < 2; mi++)
#pragma unroll
                for (int ni = 0; ni < 8; ni++) {
                    uint32_t b0 = bF[ni >> 1][(ni & 1)];
                    uint32_t b1 = bF[ni >> 1][(ni & 1) + 2];
                    MMA_BF16(acc[mi][ni], aF[mi], b0, b1);
                }
        }
        __syncthreads();
    }

    // epilogue -> fp32 Hall
#pragma unroll
    for (int mi = 0; mi < 2; mi++) {
        int row0 = m0 + wm + mi * 16 + (lane >> 2);
#pragma unroll
        for (int half = 0; half < 2; half++) {
            int gr = row0 + half * 8;
            if (gr < NN) {
                float* base = g_Hall + ((size_t)gr * NR + r) * DIM + wn + (lane & 3) * 2;
#pragma unroll
                for (int ni = 0; ni < 8; ni++)
                    *(float2*)(base + ni * 8) =
                        make_float2(acc[mi][ni][half * 2], acc[mi][ni][half * 2 + 1]);
            }
        }
    }
}

// ---------------- out[n,:] = bias (vectorized) ----------------
__global__ void k_init(const float* __restrict__ bias, int whichOut) {
    float4* out = (float4*)((whichOut == 1) ? g_hA : g_hB);
    size_t idx = (size_t)blockIdx.x * blockDim.x + threadIdx.x;   // NN*32
    if (idx < (size_t)NN * 32)
        out[idx] = ((const float4*)bias)[idx & 31];
}

// ---------------- scatter: out[dst] += Hall[src, etype] ----------------
__global__ void k_scatter(const int* __restrict__ src, const int* __restrict__ dst,
                          const int* __restrict__ et, int whichOut) {
    float* out = (whichOut == 1) ? g_hA : g_hB;
    int e = blockIdx.x * 8 + (threadIdx.x >> 5);
    if (e >= NE) return;
    int lane = threadIdx.x & 31;
    int s = __ldg(src + e), d = __ldg(dst + e), r = __ldg(et + e);
    float4 v = ((const float4*)(g_Hall + ((size_t)s * NR + r) * DIM))[lane];
    float* o = out + (size_t)d * DIM + lane * 4;
    asm volatile("red.global.add.v4.f32 [%0], {%1,%2,%3,%4};"
                 :: "l"(o), "f"(v.x), "f"(v.y), "f"(v.z), "f"(v.w) : "memory");
}

// ---------------- pooling ----------------
__global__ void k_poolinit() {
    int idx = blockIdx.x * blockDim.x + threadIdx.x;
    if (idx < NG) { g_gmax[idx] = -__int_as_float(0x7f800000); g_gsum[idx] = 0.f; }
    if (idx < NG * DIM) g_read[idx] = 0.f;
}

__global__ void k_gate(const float* __restrict__ gw, const float* __restrict__ gb,
                       const int* __restrict__ n2g) {
    int n = blockIdx.x * 8 + (threadIdx.x >> 5);
    if (n >= NN) return;
    int lane = threadIdx.x & 31;
    float4 hv = ((const float4*)(g_hA + (size_t)n * DIM))[lane];
    float4 wv = ((const float4*)gw)[lane];
    float s = hv.x * wv.x + hv.y * wv.y + hv.z * wv.z + hv.w * wv.w;
#pragma unroll
    for (int o = 16; o; o >>= 1) s += __shfl_xor_sync(0xffffffffu, s, o);
    if (lane == 0) {
        s += gb[0];
        g_gate[n] = s;
        int g = n2g[n];
        int* ia = (int*)&g_gmax[g];
        int old = *ia;
        while (__int_as_float(old) < s) {
            int prev = atomicCAS(ia, old, __float_as_int(s));
            if (prev == old) break;
            old = prev;
        }
    }
}

__global__ void k_expsum(const int* __restrict__ n2g) {
    int n = blockIdx.x * blockDim.x + threadIdx.x;
    if (n >= NN) return;
    int g = n2g[n];
    float e = expf(g_gate[n] - g_gmax[g]);
    g_gate[n] = e;
    atomicAdd(&g_gsum[g], e);
}

__global__ void k_readout(const int* __restrict__ n2g) {
    int n = blockIdx.x * 8 + (threadIdx.x >> 5);
    if (n >= NN) return;
    int lane = threadIdx.x & 31;
    int g = n2g[n];
    float w = g_gate[n] / g_gsum[g];
    float4 hv = ((const float4*)(g_hA + (size_t)n * DIM))[lane];
    float* o = g_read + g * DIM + lane * 4;
    asm volatile("red.global.add.v4.f32 [%0], {%1,%2,%3,%4};"
                 :: "l"(o), "f"(hv.x * w), "f"(hv.y * w), "f"(hv.z * w), "f"(hv.w * w)
                 : "memory");
}

// ---------------- MLP head ----------------
__global__ void k_mlp(const float* __restrict__ fc1_w, const float* __restrict__ fc1_b,
                      const float* __restrict__ fc2_w, const float* __restrict__ fc2_b,
                      const float* __restrict__ fc3_w, const float* __restrict__ fc3_b,
                      float* __restrict__ out) {
    int g = blockIdx.x;
    int t = threadIdx.x;
    __shared__ float r[DIM];
    __shared__ float z1[100];
    __shared__ float z2[64];
    r[t] = g_read[g * DIM + t];
    __syncthreads();
    if (t < 100) {
        float s = fc1_b[t];
        for (int i = 0; i < DIM; i++) s = fmaf(r[i], fc1_w[i * 100 + t], s);
        z1[t] = fmaxf(s, 0.f);
    }
    __syncthreads();
    if (t < 64) {
        float s = fc2_b[t];
        for (int i = 0; i < 100; i++) s = fmaf(z1[i], fc2_w[i * 64 + t], s);
        z2[t] = fmaxf(s, 0.f);
    }
    __syncthreads();
    if (t == 0) {
        float s = fc3_b[0];
        for (int i = 0; i < 64; i++) s = fmaf(z2[i], fc3_w[i], s);
        out[g] = 1.f / (1.f + expf(-s));
    }
}

// ---------------- host launcher ----------------
extern "C" void kernel_launch(void* const* d_in, const int* in_sizes, int n_in,
                              void* d_out, int out_size) {
    const float *features, *bases1, *comp1, *bias1, *bases2, *comp2, *bias2;
    const float *bases3, *comp3, *bias3, *gate_w, *gate_b;
    const float *fc1_w, *fc1_b, *fc2_w, *fc2_b, *fc3_w, *fc3_b;
    const int *src, *dst, *etype, *n2g;

    if (in_sizes[1] == NE) {
        features = (const float*)d_in[0];
        src      = (const int*)d_in[1];
        dst      = (const int*)d_in[2];
        etype    = (const int*)d_in[3];
        n2g      = (const int*)d_in[4];
        bases1 = (const float*)d_in[5];  comp1 = (const float*)d_in[6];  bias1 = (const float*)d_in[7];
        bases2 = (const float*)d_in[8];  comp2 = (const float*)d_in[9];  bias2 = (const float*)d_in[10];
        bases3 = (const float*)d_in[11]; comp3 = (const float*)d_in[12]; bias3 = (const float*)d_in[13];
        gate_w = (const float*)d_in[14]; gate_b = (const float*)d_in[15];
        fc1_w = (const float*)d_in[16]; fc1_b = (const float*)d_in[17];
        fc2_w = (const float*)d_in[18]; fc2_b = (const float*)d_in[19];
        fc3_w = (const float*)d_in[20]; fc3_b = (const float*)d_in[21];
    } else {
        features = (const float*)d_in[0];
        bases1 = (const float*)d_in[1];  comp1 = (const float*)d_in[2];  bias1 = (const float*)d_in[3];
        bases2 = (const float*)d_in[4];  comp2 = (const float*)d_in[5];  bias2 = (const float*)d_in[6];
        bases3 = (const float*)d_in[7];  comp3 = (const float*)d_in[8];  bias3 = (const float*)d_in[9];
        gate_w = (const float*)d_in[10]; gate_b = (const float*)d_in[11];
        fc1_w = (const float*)d_in[12]; fc1_b = (const float*)d_in[13];
        fc2_w = (const float*)d_in[14]; fc2_b = (const float*)d_in[15];
        fc3_w = (const float*)d_in[16]; fc3_b = (const float*)d_in[17];
        src   = (const int*)d_in[18];
        dst   = (const int*)d_in[19];
        etype = (const int*)d_in[20];
        n2g   = (const int*)d_in[21];
    }
    float* out = (float*)d_out;

    const dim3 gemm_grid((NN + 127) / 128, NR);          // 391 x 8 (R4 ordering)
    const dim3 splitw_grid(64, NR);
    const int split_blocks = (NN * 32 + 255) / 256;      // 6250
    const int scat_blocks = NE / 8;
    const int node_warp_blocks = NN / 8;

    // ---- layer 1: features -> g_hA
    k_splitw<<<splitw_grid, 256>>>(bases1, comp1);
    k_split<<<split_blocks, 256>>>(features, 0, 0);
    k_gemm_mma<<<gemm_grid, 256>>>();
    k_init<<<split_blocks, 256>>>(bias1, 1);
    k_scatter<<<scat_blocks, 256>>>(src, dst, etype, 1);
    // ---- layer 2: relu(g_hA) -> g_hB
    k_splitw<<<splitw_grid, 256>>>(bases2, comp2);
    k_split<<<split_blocks, 256>>>(features, 1, 1);
    k_gemm_mma<<<gemm_grid, 256>>>();
    k_init<<<split_blocks, 256>>>(bias2, 2);
    k_scatter<<<scat_blocks, 256>>>(src, dst, etype, 2);
    // ---- layer 3: relu(g_hB) -> g_hA
    k_splitw<<<splitw_grid, 256>>>(bases3, comp3);
    k_split<<<split_blocks, 256>>>(features, 2, 1);
    k_gemm_mma<<<gemm_grid, 256>>>();
    k_init<<<split_blocks, 256>>>(bias3, 1);
    k_scatter<<<scat_blocks, 256>>>(src, dst, etype, 1);
    // ---- attention pooling on g_hA
    k_poolinit<<<(NG * DIM + 255) / 256, 256>>>();
    k_gate<<<node_warp_blocks, 256>>>(gate_w, gate_b, n2g);
    k_expsum<<<(NN + 255) / 256, 256>>>(n2g);
    k_readout<<<node_warp_blocks, 256>>>(n2g);
    // ---- MLP head
    k_mlp<<<NG, DIM>>>(fc1_w, fc1_b, fc2_w, fc2_b, fc3_w, fc3_b, out);
}

// round 8
// speedup vs baseline: 1.2568x; 1.1234x over previous
#include <cuda_runtime.h>
#include <cuda_bf16.h>
#include <cstdint>

#define NN 50000
#define NE 600000
#define DIM 128
#define NR 8
#define NB 8
#define NG 256
#define KA 256       // A2: [hi | lo]
#define KW 384       // W2: [Whi ; Whi ; Wlo]

// ---------------- static device scratch ----------------
__device__ __nv_bfloat16 g_A2[(size_t)NN * KA];              // split input, 25.6MB
__device__ __nv_bfloat16 g_W2[NR * DIM * KW];                // split transposed weights
__device__ float g_Hall[(size_t)NN * NR * DIM];              // 204.8 MB fp32
__device__ float g_hA[(size_t)NN * DIM];
__device__ float g_hB[(size_t)NN * DIM];
__device__ float g_gate[NN];
__device__ float g_gmax[NG];
__device__ float g_gsum[NG];
__device__ float g_read[NG * DIM];
// CSR by dst (rebuilt every launch; edges identical across layers)
__device__ int g_rowptr[NN + 1];
__device__ int g_cursor[NN];
__device__ int g_eidx[NE];                                   // src*8 + etype

// ---------------- PTX helpers (Ampere-class ISA only) ----------------
__device__ __forceinline__ uint32_t smem_u32(const void* p) {
    uint32_t a;
    asm("{ .reg .u64 t; cvta.to.shared.u64 t, %1; cvt.u32.u64 %0, t; }" : "=r"(a) : "l"(p));
    return a;
}
#define CP_ASYNC16(dst, src) \
    asm volatile("cp.async.cg.shared.global [%0], [%1], 16;" :: "r"(dst), "l"(src))
#define CP_COMMIT() asm volatile("cp.async.commit_group;" ::: "memory")
#define CP_WAIT0()  asm volatile("cp.async.wait_group 0;" ::: "memory")

#define LDMX4(f, addr) asm volatile( \
    "ldmatrix.sync.aligned.m8n8.x4.shared.b16 {%0,%1,%2,%3}, [%4];" \
    : "=r"((f)[0]), "=r"((f)[1]), "=r"((f)[2]), "=r"((f)[3]) : "r"(addr))

#define MMA_BF16(d, a, b0, b1) asm volatile( \
    "mma.sync.aligned.m16n8k16.row.col.f32.bf16.bf16.f32 " \
    "{%0,%1,%2,%3}, {%4,%5,%6,%7}, {%8,%9}, {%0,%1,%2,%3};" \
    : "+f"((d)[0]), "+f"((d)[1]), "+f"((d)[2]), "+f"((d)[3]) \
    : "r"((a)[0]), "r"((a)[1]), "r"((a)[2]), "r"((a)[3]), "r"(b0), "r"(b1))

// ---------------- CSR build ----------------
__global__ void k_hist0() {
    int i = blockIdx.x * 256 + threadIdx.x;
    if (i < NN) g_cursor[i] = 0;
}
__global__ void k_hist(const int* __restrict__ dst) {
    int e = blockIdx.x * 256 + threadIdx.x;
    if (e < NE) atomicAdd(&g_cursor[__ldg(dst + e)], 1);
}
// single-block exclusive scan over 50000 counts -> rowptr, cursor reset
__global__ __launch_bounds__(1024) void k_scan() {
    __shared__ int wsum[32];
    __shared__ int s_carry;
    const int tid = threadIdx.x;
    const int lane = tid & 31, wid = tid >> 5;
    if (tid == 0) s_carry = 0;
    __syncthreads();
    for (int base = 0; base < NN; base += 1024) {
        int i = base + tid;
        int v = (i < NN) ? g_cursor[i] : 0;
        // inclusive warp scan
        int x = v;
#pragma unroll
        for (int o = 1; o < 32; o <<= 1) {
            int y = __shfl_up_sync(0xffffffffu, x, o);
            if (lane >= o) x += y;
        }
        if (lane == 31) wsum[wid] = x;
        __syncthreads();
        if (wid == 0) {
            int w = (lane < 32) ? wsum[lane] : 0;
#pragma unroll
            for (int o = 1; o < 32; o <<= 1) {
                int y = __shfl_up_sync(0xffffffffu, w, o);
                if (lane >= o) w += y;
            }
            wsum[lane] = w;
        }
        __syncthreads();
        int incl = x + (wid > 0 ? wsum[wid - 1] : 0) + s_carry;
        int excl = incl - v;
        if (i < NN) { g_rowptr[i] = excl; g_cursor[i] = excl; }
        if (i == NN - 1) g_rowptr[NN] = incl;
        __syncthreads();
        if (tid == 1023) s_carry = incl - (base + 1024 <= NN ? 0 : 0) ; // incl of last element
        // note: when i >= NN, v=0 so incl of tid1023 == total so far
        __syncthreads();
    }
}
__global__ void k_fill(const int* __restrict__ src, const int* __restrict__ dst,
                       const int* __restrict__ et) {
    int e = blockIdx.x * 256 + threadIdx.x;
    if (e >= NE) return;
    int d = __ldg(dst + e);
    int pos = atomicAdd(&g_cursor[d], 1);
    g_eidx[pos] = __ldg(src + e) * NR + __ldg(et + e);
}

// ---------------- split weights ----------------
__global__ void k_splitw(const float* __restrict__ bases, const float* __restrict__ comp) {
    int r = blockIdx.y;
    int t = blockIdx.x * 256 + threadIdx.x;
    if (t >= DIM * DIM) return;
    int k = t >> 7, n = t & 127;
    float s = 0.f;
#pragma unroll
    for (int b = 0; b < NB; b++)
        s = fmaf(comp[r * NB + b], bases[((size_t)b * DIM + k) * DIM + n], s);
    __nv_bfloat16 hi = __float2bfloat16(s);
    __nv_bfloat16 lo = __float2bfloat16(s - __bfloat162float(hi));
    __nv_bfloat16* w = g_W2 + ((size_t)r * DIM + n) * KW;
    w[k] = hi; w[128 + k] = hi; w[256 + k] = lo;
}

// ---------------- split activations: A2[n] = [hi | lo] ----------------
__global__ void k_split(const float* __restrict__ Aext, int whichA, int relu_in) {
    const float* __restrict__ A = (whichA == 0) ? Aext : (whichA == 1 ? g_hA : g_hB);
    size_t idx = (size_t)blockIdx.x * blockDim.x + threadIdx.x;   // NN*32
    if (idx >= (size_t)NN * 32) return;
    size_t n = idx >> 5;
    int c4 = (int)(idx & 31);
    float4 v = ((const float4*)(A + n * DIM))[c4];
    if (relu_in) {
        v.x = fmaxf(v.x, 0.f); v.y = fmaxf(v.y, 0.f);
        v.z = fmaxf(v.z, 0.f); v.w = fmaxf(v.w, 0.f);
    }
    __nv_bfloat16 h[4], l[4];
    float f[4] = {v.x, v.y, v.z, v.w};
#pragma unroll
    for (int i = 0; i < 4; i++) {
        h[i] = __float2bfloat16(f[i]);
        l[i] = __float2bfloat16(f[i] - __bfloat162float(h[i]));
    }
    __nv_bfloat16* a2 = g_A2 + n * KA + c4 * 4;
    *(uint2*)(a2)       = *(uint2*)h;
    *(uint2*)(a2 + 128) = *(uint2*)l;
}

// ---------------- HMMA GEMM (proven R4/R7 config); grid = (NR, mtiles) ----------------
__global__ __launch_bounds__(256, 2) void k_gemm_mma() {
    constexpr int SP = 72;                                // bf16 per smem row
    __shared__ __nv_bfloat16 sA[128 * SP];
    __shared__ __nv_bfloat16 sB[128 * SP];

    const int tid = threadIdx.x;
    const int wid = tid >> 5, lane = tid & 31;
    const int r = blockIdx.x;                             // relation = fast index
    const int m0 = blockIdx.y * 128;
    const int wm = (wid & 3) * 32;
    const int wn = (wid >> 2) * 64;

    const __nv_bfloat16* __restrict__ Ag = g_A2;
    const __nv_bfloat16* __restrict__ Bg = g_W2 + (size_t)r * DIM * KW;

    // A offsets in compact [hi|lo] for the 6 BK=64 W-chunks: hi hi lo lo hi hi
    const int a_off[6] = {0, 64, 128, 192, 0, 64};

    float acc[2][8][4];
#pragma unroll
    for (int mi = 0; mi < 2; mi++)
#pragma unroll
        for (int ni = 0; ni < 8; ni++)
#pragma unroll
            for (int q = 0; q < 4; q++) acc[mi][ni][q] = 0.f;

    const uint32_t sA_b = smem_u32(sA), sB_b = smem_u32(sB);
    const int lrow = (lane & 15);
    const int lcol = (lane & 16) ? 8 : 0;

    for (int kc = 0; kc < 6; kc++) {
#pragma unroll
        for (int i = 0; i < 4; i++) {
            int id = tid + i * 256;
            int row = id >> 3, seg = id & 7;
            int gr = m0 + row; if (gr >= NN) gr = NN - 1;
            CP_ASYNC16(sA_b + (row * SP + seg * 8) * 2,
                       Ag + (size_t)gr * KA + a_off[kc] + seg * 8);
            CP_ASYNC16(sB_b + (row * SP + seg * 8) * 2,
                       Bg + (size_t)row * KW + kc * 64 + seg * 8);
        }
        CP_COMMIT(); CP_WAIT0();
        __syncthreads();

#pragma unroll
        for (int ks = 0; ks < 4; ks++) {
            const int k0 = ks * 16;
            uint32_t aF[2][4], bF[4][4];
#pragma unroll
            for (int mi = 0; mi < 2; mi++)
                LDMX4(aF[mi], sA_b + ((wm + mi * 16 + lrow) * SP + k0 + lcol) * 2);
#pragma unroll
            for (int g = 0; g < 4; g++)
                LDMX4(bF[g], sB_b + ((wn + g * 16 + lrow) * SP + k0 + lcol) * 2);
#pragma unroll
            for (int mi = 0; mi < 2; mi++)
#pragma unroll
                for (int ni = 0; ni < 8; ni++) {
                    uint32_t b0 = bF[ni >> 1][(ni & 1)];
                    uint32_t b1 = bF[ni >> 1][(ni & 1) + 2];
                    MMA_BF16(acc[mi][ni], aF[mi], b0, b1);
                }
        }
        __syncthreads();
    }

    // epilogue -> fp32 Hall
#pragma unroll
    for (int mi = 0; mi < 2; mi++) {
        int row0 = m0 + wm + mi * 16 + (lane >> 2);
#pragma unroll
        for (int half = 0; half < 2; half++) {
            int gr = row0 + half * 8;
            if (gr < NN) {
                float* base = g_Hall + ((size_t)gr * NR + r) * DIM + wn + (lane & 3) * 2;
#pragma unroll
                for (int ni = 0; ni < 8; ni++)
                    *(float2*)(base + ni * 8) =
                        make_float2(acc[mi][ni][half * 2], acc[mi][ni][half * 2 + 1]);
            }
        }
    }
}

// ---------------- gather: out[n] = bias + sum_{e in CSR[n]} Hall[eidx[e]] ----------------
__global__ void k_gather(const float* __restrict__ bias, int whichOut) {
    float* out = (whichOut == 1) ? g_hA : g_hB;
    int n = blockIdx.x * 8 + (threadIdx.x >> 5);
    if (n >= NN) return;
    int lane = threadIdx.x & 31;
    float4 acc = ((const float4*)bias)[lane];
    int beg = __ldg(&g_rowptr[n]), end = __ldg(&g_rowptr[n + 1]);
    for (int e = beg; e < end; e++) {
        int p = __ldg(&g_eidx[e]);
        float4 v = ((const float4*)(g_Hall + (size_t)p * DIM))[lane];
        acc.x += v.x; acc.y += v.y; acc.z += v.z; acc.w += v.w;
    }
    ((float4*)(out + (size_t)n * DIM))[lane] = acc;
}

// ---------------- pooling ----------------
__global__ void k_poolinit() {
    int idx = blockIdx.x * blockDim.x + threadIdx.x;
    if (idx < NG) { g_gmax[idx] = -__int_as_float(0x7f800000); g_gsum[idx] = 0.f; }
    if (idx < NG * DIM) g_read[idx] = 0.f;
}

__global__ void k_gate(const float* __restrict__ gw, const float* __restrict__ gb,
                       const int* __restrict__ n2g) {
    int n = blockIdx.x * 8 + (threadIdx.x >> 5);
    if (n >= NN) return;
    int lane = threadIdx.x & 31;
    float4 hv = ((const float4*)(g_hA + (size_t)n * DIM))[lane];
    float4 wv = ((const float4*)gw)[lane];
    float s = hv.x * wv.x + hv.y * wv.y + hv.z * wv.z + hv.w * wv.w;
#pragma unroll
    for (int o = 16; o; o >>= 1) s += __shfl_xor_sync(0xffffffffu, s, o);
    if (lane == 0) {
        s += gb[0];
        g_gate[n] = s;
        int g = n2g[n];
        int* ia = (int*)&g_gmax[g];
        int old = *ia;
        while (__int_as_float(old) < s) {
            int prev = atomicCAS(ia, old, __float_as_int(s));
            if (prev == old) break;
            old = prev;
        }
    }
}

__global__ void k_expsum(const int* __restrict__ n2g) {
    int n = blockIdx.x * blockDim.x + threadIdx.x;
    if (n >= NN) return;
    int g = n2g[n];
    float e = expf(g_gate[n] - g_gmax[g]);
    g_gate[n] = e;
    atomicAdd(&g_gsum[g], e);
}

__global__ void k_readout(const int* __restrict__ n2g) {
    int n = blockIdx.x * 8 + (threadIdx.x >> 5);
    if (n >= NN) return;
    int lane = threadIdx.x & 31;
    int g = n2g[n];
    float w = g_gate[n] / g_gsum[g];
    float4 hv = ((const float4*)(g_hA + (size_t)n * DIM))[lane];
    float* o = g_read + g * DIM + lane * 4;
    asm volatile("red.global.add.v4.f32 [%0], {%1,%2,%3,%4};"
                 :: "l"(o), "f"(hv.x * w), "f"(hv.y * w), "f"(hv.z * w), "f"(hv.w * w)
                 : "memory");
}

// ---------------- MLP head ----------------
__global__ void k_mlp(const float* __restrict__ fc1_w, const float* __restrict__ fc1_b,
                      const float* __restrict__ fc2_w, const float* __restrict__ fc2_b,
                      const float* __restrict__ fc3_w, const float* __restrict__ fc3_b,
                      float* __restrict__ out) {
    int g = blockIdx.x;
    int t = threadIdx.x;
    __shared__ float r[DIM];
    __shared__ float z1[100];
    __shared__ float z2[64];
    r[t] = g_read[g * DIM + t];
    __syncthreads();
    if (t < 100) {
        float s = fc1_b[t];
        for (int i = 0; i < DIM; i++) s = fmaf(r[i], fc1_w[i * 100 + t], s);
        z1[t] = fmaxf(s, 0.f);
    }
    __syncthreads();
    if (t < 64) {
        float s = fc2_b[t];
        for (int i = 0; i < 100; i++) s = fmaf(z1[i], fc2_w[i * 64 + t], s);
        z2[t] = fmaxf(s, 0.f);
    }
    __syncthreads();
    if (t == 0) {
        float s = fc3_b[0];
        for (int i = 0; i < 64; i++) s = fmaf(z2[i], fc3_w[i], s);
        out[g] = 1.f / (1.f + expf(-s));
    }
}

// ---------------- host launcher ----------------
extern "C" void kernel_launch(void* const* d_in, const int* in_sizes, int n_in,
                              void* d_out, int out_size) {
    const float *features, *bases1, *comp1, *bias1, *bases2, *comp2, *bias2;
    const float *bases3, *comp3, *bias3, *gate_w, *gate_b;
    const float *fc1_w, *fc1_b, *fc2_w, *fc2_b, *fc3_w, *fc3_b;
    const int *src, *dst, *etype, *n2g;

    if (in_sizes[1] == NE) {
        features = (const float*)d_in[0];
        src      = (const int*)d_in[1];
        dst      = (const int*)d_in[2];
        etype    = (const int*)d_in[3];
        n2g      = (const int*)d_in[4];
        bases1 = (const float*)d_in[5];  comp1 = (const float*)d_in[6];  bias1 = (const float*)d_in[7];
        bases2 = (const float*)d_in[8];  comp2 = (const float*)d_in[9];  bias2 = (const float*)d_in[10];
        bases3 = (const float*)d_in[11]; comp3 = (const float*)d_in[12]; bias3 = (const float*)d_in[13];
        gate_w = (const float*)d_in[14]; gate_b = (const float*)d_in[15];
        fc1_w = (const float*)d_in[16]; fc1_b = (const float*)d_in[17];
        fc2_w = (const float*)d_in[18]; fc2_b = (const float*)d_in[19];
        fc3_w = (const float*)d_in[20]; fc3_b = (const float*)d_in[21];
    } else {
        features = (const float*)d_in[0];
        bases1 = (const float*)d_in[1];  comp1 = (const float*)d_in[2];  bias1 = (const float*)d_in[3];
        bases2 = (const float*)d_in[4];  comp2 = (const float*)d_in[5];  bias2 = (const float*)d_in[6];
        bases3 = (const float*)d_in[7];  comp3 = (const float*)d_in[8];  bias3 = (const float*)d_in[9];
        gate_w = (const float*)d_in[10]; gate_b = (const float*)d_in[11];
        fc1_w = (const float*)d_in[12]; fc1_b = (const float*)d_in[13];
        fc2_w = (const float*)d_in[14]; fc2_b = (const float*)d_in[15];
        fc3_w = (const float*)d_in[16]; fc3_b = (const float*)d_in[17];
        src   = (const int*)d_in[18];
        dst   = (const int*)d_in[19];
        etype = (const int*)d_in[20];
        n2g   = (const int*)d_in[21];
    }
    float* out = (float*)d_out;

    const dim3 gemm_grid(NR, (NN + 127) / 128);          // relation fastest -> A L2 reuse
    const dim3 splitw_grid(64, NR);
    const int split_blocks = (NN * 32 + 255) / 256;      // 6250
    const int node_warp_blocks = NN / 8;                 // 6250
    const int edge_blocks = (NE + 255) / 256;            // 2344
    const int node_blocks = (NN + 255) / 256;            // 196

    // ---- CSR by dst (once; shared by all 3 layers)
    k_hist0<<<node_blocks, 256>>>();
    k_hist<<<edge_blocks, 256>>>(dst);
    k_scan<<<1, 1024>>>();
    k_fill<<<edge_blocks, 256>>>(src, dst, etype);

    // ---- layer 1: features -> g_hA
    k_splitw<<<splitw_grid, 256>>>(bases1, comp1);
    k_split<<<split_blocks, 256>>>(features, 0, 0);
    k_gemm_mma<<<gemm_grid, 256>>>();
    k_gather<<<node_warp_blocks, 256>>>(bias1, 1);
    // ---- layer 2: relu(g_hA) -> g_hB
    k_splitw<<<splitw_grid, 256>>>(bases2, comp2);
    k_split<<<split_blocks, 256>>>(features, 1, 1);
    k_gemm_mma<<<gemm_grid, 256>>>();
    k_gather<<<node_warp_blocks, 256>>>(bias2, 2);
    // ---- layer 3: relu(g_hB) -> g_hA
    k_splitw<<<splitw_grid, 256>>>(bases3, comp3);
    k_split<<<split_blocks, 256>>>(features, 2, 1);
    k_gemm_mma<<<gemm_grid, 256>>>();
    k_gather<<<node_warp_blocks, 256>>>(bias3, 1);
    // ---- attention pooling on g_hA
    k_poolinit<<<(NG * DIM + 255) / 256, 256>>>();
    k_gate<<<node_warp_blocks, 256>>>(gate_w, gate_b, n2g);
    k_expsum<<<(NN + 255) / 256, 256>>>(n2g);
    k_readout<<<node_warp_blocks, 256>>>(n2g);
    // ---- MLP head
    k_mlp<<<NG, DIM>>>(fc1_w, fc1_b, fc2_w, fc2_b, fc3_w, fc3_b, out);
}

// round 9
// speedup vs baseline: 1.2717x; 1.0118x over previous
#include <cuda_runtime.h>
#include <cuda_bf16.h>
#include <cstdint>

#define NN 50000
#define NE 600000
#define DIM 128
#define NR 8
#define NB 8
#define NG 256
#define KA 256       // A2: [hi | lo]
#define KW 384       // W2: [Whi ; Whi ; Wlo]

// ---------------- static device scratch ----------------
__device__ __nv_bfloat16 g_A2[(size_t)NN * KA];              // split input, 25.6MB
__device__ __nv_bfloat16 g_W2[NR * DIM * KW];                // split transposed weights
__device__ float g_Hall[(size_t)NN * NR * DIM];              // 204.8 MB fp32
__device__ float g_hA[(size_t)NN * DIM];                     // layer-3 output (pooling input)
__device__ float g_gate[NN];
__device__ float g_gmax[NG];
__device__ float g_gsum[NG];
__device__ float g_read[NG * DIM];
// CSR by dst (rebuilt every launch; edges identical across layers)
__device__ int g_rowptr[NN + 1];
__device__ int g_cursor[NN];
__device__ int g_eidx[NE];                                   // src*8 + etype

// ---------------- PTX helpers (Ampere-class ISA only) ----------------
__device__ __forceinline__ uint32_t smem_u32(const void* p) {
    uint32_t a;
    asm("{ .reg .u64 t; cvta.to.shared.u64 t, %1; cvt.u32.u64 %0, t; }" : "=r"(a) : "l"(p));
    return a;
}
#define CP_ASYNC16(dst, src) \
    asm volatile("cp.async.cg.shared.global [%0], [%1], 16;" :: "r"(dst), "l"(src))
#define CP_COMMIT() asm volatile("cp.async.commit_group;" ::: "memory")
#define CP_WAIT0()  asm volatile("cp.async.wait_group 0;" ::: "memory")

#define LDMX4(f, addr) asm volatile( \
    "ldmatrix.sync.aligned.m8n8.x4.shared.b16 {%0,%1,%2,%3}, [%4];" \
    : "=r"((f)[0]), "=r"((f)[1]), "=r"((f)[2]), "=r"((f)[3]) : "r"(addr))

#define MMA_BF16(d, a, b0, b1) asm volatile( \
    "mma.sync.aligned.m16n8k16.row.col.f32.bf16.bf16.f32 " \
    "{%0,%1,%2,%3}, {%4,%5,%6,%7}, {%8,%9}, {%0,%1,%2,%3};" \
    : "+f"((d)[0]), "+f"((d)[1]), "+f"((d)[2]), "+f"((d)[3]) \
    : "r"((a)[0]), "r"((a)[1]), "r"((a)[2]), "r"((a)[3]), "r"(b0), "r"(b1))

// ---------------- CSR build ----------------
__global__ void k_hist0() {
    int i = blockIdx.x * 256 + threadIdx.x;
    if (i < NN) g_cursor[i] = 0;
}
__global__ void k_hist(const int* __restrict__ dst) {
    int e = blockIdx.x * 256 + threadIdx.x;
    if (e < NE) atomicAdd(&g_cursor[__ldg(dst + e)], 1);
}
// single-block exclusive scan over NN counts -> rowptr, cursor = excl
__global__ __launch_bounds__(1024) void k_scan() {
    __shared__ int wsum[32];
    __shared__ int s_carry;
    const int tid = threadIdx.x;
    const int lane = tid & 31, wid = tid >> 5;
    if (tid == 0) s_carry = 0;
    __syncthreads();
    for (int base = 0; base < NN; base += 1024) {
        int i = base + tid;
        int v = (i < NN) ? g_cursor[i] : 0;
        int x = v;
#pragma unroll
        for (int o = 1; o < 32; o <<= 1) {
            int y = __shfl_up_sync(0xffffffffu, x, o);
            if (lane >= o) x += y;
        }
        if (lane == 31) wsum[wid] = x;
        __syncthreads();
        if (wid == 0) {
            int w = (lane < 32) ? wsum[lane] : 0;
#pragma unroll
            for (int o = 1; o < 32; o <<= 1) {
                int y = __shfl_up_sync(0xffffffffu, w, o);
                if (lane >= o) w += y;
            }
            wsum[lane] = w;
        }
        __syncthreads();
        int incl = x + (wid > 0 ? wsum[wid - 1] : 0) + s_carry;
        int excl = incl - v;
        if (i < NN) { g_rowptr[i] = excl; g_cursor[i] = excl; }
        if (i == NN - 1) g_rowptr[NN] = incl;
        __syncthreads();
        if (tid == 1023) s_carry = incl;
        __syncthreads();
    }
}
__global__ void k_fill(const int* __restrict__ src, const int* __restrict__ dst,
                       const int* __restrict__ et) {
    int e = blockIdx.x * 256 + threadIdx.x;
    if (e >= NE) return;
    int d = __ldg(dst + e);
    int pos = atomicAdd(&g_cursor[d], 1);
    g_eidx[pos] = __ldg(src + e) * NR + __ldg(et + e);
}

// ---------------- split weights ----------------
__global__ void k_splitw(const float* __restrict__ bases, const float* __restrict__ comp) {
    int r = blockIdx.y;
    int t = blockIdx.x * 256 + threadIdx.x;
    if (t >= DIM * DIM) return;
    int k = t >> 7, n = t & 127;
    float s = 0.f;
#pragma unroll
    for (int b = 0; b < NB; b++)
        s = fmaf(comp[r * NB + b], bases[((size_t)b * DIM + k) * DIM + n], s);
    __nv_bfloat16 hi = __float2bfloat16(s);
    __nv_bfloat16 lo = __float2bfloat16(s - __bfloat162float(hi));
    __nv_bfloat16* w = g_W2 + ((size_t)r * DIM + n) * KW;
    w[k] = hi; w[128 + k] = hi; w[256 + k] = lo;
}

// ---------------- split activations (features only): A2[n] = [hi | lo] ----------------
__global__ void k_split(const float* __restrict__ A) {
    size_t idx = (size_t)blockIdx.x * blockDim.x + threadIdx.x;   // NN*32
    if (idx >= (size_t)NN * 32) return;
    size_t n = idx >> 5;
    int c4 = (int)(idx & 31);
    float4 v = ((const float4*)(A + n * DIM))[c4];
    __nv_bfloat16 h[4], l[4];
    float f[4] = {v.x, v.y, v.z, v.w};
#pragma unroll
    for (int i = 0; i < 4; i++) {
        h[i] = __float2bfloat16(f[i]);
        l[i] = __float2bfloat16(f[i] - __bfloat162float(h[i]));
    }
    __nv_bfloat16* a2 = g_A2 + n * KA + c4 * 4;
    *(uint2*)(a2)       = *(uint2*)h;
    *(uint2*)(a2 + 128) = *(uint2*)l;
}

// ---------------- HMMA GEMM (proven config); grid = (NR, mtiles) ----------------
__global__ __launch_bounds__(256, 2) void k_gemm_mma() {
    constexpr int SP = 72;                                // bf16 per smem row
    __shared__ __nv_bfloat16 sA[128 * SP];
    __shared__ __nv_bfloat16 sB[128 * SP];

    const int tid = threadIdx.x;
    const int wid = tid >> 5, lane = tid & 31;
    const int r = blockIdx.x;                             // relation = fast index
    const int m0 = blockIdx.y * 128;
    const int wm = (wid & 3) * 32;
    const int wn = (wid >> 2) * 64;

    const __nv_bfloat16* __restrict__ Ag = g_A2;
    const __nv_bfloat16* __restrict__ Bg = g_W2 + (size_t)r * DIM * KW;

    const int a_off[6] = {0, 64, 128, 192, 0, 64};        // hi hi lo lo hi hi

    float acc[2][8][4];
#pragma unroll
    for (int mi = 0; mi < 2; mi++)
#pragma unroll
        for (int ni = 0; ni < 8; ni++)
#pragma unroll
            for (int q = 0; q < 4; q++) acc[mi][ni][q] = 0.f;

    const uint32_t sA_b = smem_u32(sA), sB_b = smem_u32(sB);
    const int lrow = (lane & 15);
    const int lcol = (lane & 16) ? 8 : 0;

    for (int kc = 0; kc < 6; kc++) {
#pragma unroll
        for (int i = 0; i < 4; i++) {
            int id = tid + i * 256;
            int row = id >> 3, seg = id & 7;
            int gr = m0 + row; if (gr >= NN) gr = NN - 1;
            CP_ASYNC16(sA_b + (row * SP + seg * 8) * 2,
                       Ag + (size_t)gr * KA + a_off[kc] + seg * 8);
            CP_ASYNC16(sB_b + (row * SP + seg * 8) * 2,
                       Bg + (size_t)row * KW + kc * 64 + seg * 8);
        }
        CP_COMMIT(); CP_WAIT0();
        __syncthreads();

#pragma unroll
        for (int ks = 0; ks < 4; ks++) {
            const int k0 = ks * 16;
            uint32_t aF[2][4], bF[4][4];
#pragma unroll
            for (int mi = 0; mi < 2; mi++)
                LDMX4(aF[mi], sA_b + ((wm + mi * 16 + lrow) * SP + k0 + lcol) * 2);
#pragma unroll
            for (int g = 0; g < 4; g++)
                LDMX4(bF[g], sB_b + ((wn + g * 16 + lrow) * SP + k0 + lcol) * 2);
#pragma unroll
            for (int mi = 0; mi < 2; mi++)
#pragma unroll
                for (int ni = 0; ni < 8; ni++) {
                    uint32_t b0 = bF[ni >> 1][(ni & 1)];
                    uint32_t b1 = bF[ni >> 1][(ni & 1) + 2];
                    MMA_BF16(acc[mi][ni], aF[mi], b0, b1);
                }
        }
        __syncthreads();
    }

#pragma unroll
    for (int mi = 0; mi < 2; mi++) {
        int row0 = m0 + wm + mi * 16 + (lane >> 2);
#pragma unroll
        for (int half = 0; half < 2; half++) {
            int gr = row0 + half * 8;
            if (gr < NN) {
                float* base = g_Hall + ((size_t)gr * NR + r) * DIM + wn + (lane & 3) * 2;
#pragma unroll
                for (int ni = 0; ni < 8; ni++)
                    *(float2*)(base + ni * 8) =
                        make_float2(acc[mi][ni][half * 2], acc[mi][ni][half * 2 + 1]);
            }
        }
    }
}

// ---------------- fused gather + relu + split -> A2 (layer boundaries) ----------------
__global__ void k_gather_split(const float* __restrict__ bias) {
    int n = blockIdx.x * 8 + (threadIdx.x >> 5);
    if (n >= NN) return;
    int lane = threadIdx.x & 31;
    float4 acc = ((const float4*)bias)[lane];
    int beg = __ldg(&g_rowptr[n]), end = __ldg(&g_rowptr[n + 1]);
    for (int e = beg; e < end; e++) {
        int p = __ldg(&g_eidx[e]);
        float4 v = ((const float4*)(g_Hall + (size_t)p * DIM))[lane];
        acc.x += v.x; acc.y += v.y; acc.z += v.z; acc.w += v.w;
    }
    float f[4] = {fmaxf(acc.x, 0.f), fmaxf(acc.y, 0.f), fmaxf(acc.z, 0.f), fmaxf(acc.w, 0.f)};
    __nv_bfloat16 h[4], l[4];
#pragma unroll
    for (int i = 0; i < 4; i++) {
        h[i] = __float2bfloat16(f[i]);
        l[i] = __float2bfloat16(f[i] - __bfloat162float(h[i]));
    }
    __nv_bfloat16* a2 = g_A2 + (size_t)n * KA + lane * 4;
    *(uint2*)(a2)       = *(uint2*)h;
    *(uint2*)(a2 + 128) = *(uint2*)l;
}

// ---------------- final gather (layer 3, fp32, no relu) ----------------
__global__ void k_gather(const float* __restrict__ bias) {
    int n = blockIdx.x * 8 + (threadIdx.x >> 5);
    if (n >= NN) return;
    int lane = threadIdx.x & 31;
    float4 acc = ((const float4*)bias)[lane];
    int beg = __ldg(&g_rowptr[n]), end = __ldg(&g_rowptr[n + 1]);
    for (int e = beg; e < end; e++) {
        int p = __ldg(&g_eidx[e]);
        float4 v = ((const float4*)(g_Hall + (size_t)p * DIM))[lane];
        acc.x += v.x; acc.y += v.y; acc.z += v.z; acc.w += v.w;
    }
    ((float4*)(g_hA + (size_t)n * DIM))[lane] = acc;
}

// ---------------- pooling ----------------
__global__ void k_poolinit() {
    int idx = blockIdx.x * blockDim.x + threadIdx.x;
    if (idx < NG) { g_gmax[idx] = -__int_as_float(0x7f800000); g_gsum[idx] = 0.f; }
    if (idx < NG * DIM) g_read[idx] = 0.f;
}

__global__ void k_gate(const float* __restrict__ gw, const float* __restrict__ gb,
                       const int* __restrict__ n2g) {
    int n = blockIdx.x * 8 + (threadIdx.x >> 5);
    if (n >= NN) return;
    int lane = threadIdx.x & 31;
    float4 hv = ((const float4*)(g_hA + (size_t)n * DIM))[lane];
    float4 wv = ((const float4*)gw)[lane];
    float s = hv.x * wv.x + hv.y * wv.y + hv.z * wv.z + hv.w * wv.w;
#pragma unroll
    for (int o = 16; o; o >>= 1) s += __shfl_xor_sync(0xffffffffu, s, o);
    if (lane == 0) {
        s += gb[0];
        g_gate[n] = s;
        int g = n2g[n];
        int* ia = (int*)&g_gmax[g];
        int old = *ia;
        while (__int_as_float(old) < s) {
            int prev = atomicCAS(ia, old, __float_as_int(s));
            if (prev == old) break;
            old = prev;
        }
    }
}

__global__ void k_expsum(const int* __restrict__ n2g) {
    int n = blockIdx.x * blockDim.x + threadIdx.x;
    if (n >= NN) return;
    int g = n2g[n];
    float e = expf(g_gate[n] - g_gmax[g]);
    g_gate[n] = e;
    atomicAdd(&g_gsum[g], e);
}

__global__ void k_readout(const int* __restrict__ n2g) {
    int n = blockIdx.x * 8 + (threadIdx.x >> 5);
    if (n >= NN) return;
    int lane = threadIdx.x & 31;
    int g = n2g[n];
    float w = g_gate[n] / g_gsum[g];
    float4 hv = ((const float4*)(g_hA + (size_t)n * DIM))[lane];
    float* o = g_read + g * DIM + lane * 4;
    asm volatile("red.global.add.v4.f32 [%0], {%1,%2,%3,%4};"
                 :: "l"(o), "f"(hv.x * w), "f"(hv.y * w), "f"(hv.z * w), "f"(hv.w * w)
                 : "memory");
}

// ---------------- MLP head ----------------
__global__ void k_mlp(const float* __restrict__ fc1_w, const float* __restrict__ fc1_b,
                      const float* __restrict__ fc2_w, const float* __restrict__ fc2_b,
                      const float* __restrict__ fc3_w, const float* __restrict__ fc3_b,
                      float* __restrict__ out) {
    int g = blockIdx.x;
    int t = threadIdx.x;
    __shared__ float r[DIM];
    __shared__ float z1[100];
    __shared__ float z2[64];
    r[t] = g_read[g * DIM + t];
    __syncthreads();
    if (t < 100) {
        float s = fc1_b[t];
        for (int i = 0; i < DIM; i++) s = fmaf(r[i], fc1_w[i * 100 + t], s);
        z1[t] = fmaxf(s, 0.f);
    }
    __syncthreads();
    if (t < 64) {
        float s = fc2_b[t];
        for (int i = 0; i < 100; i++) s = fmaf(z1[i], fc2_w[i * 64 + t], s);
        z2[t] = fmaxf(s, 0.f);
    }
    __syncthreads();
    if (t == 0) {
        float s = fc3_b[0];
        for (int i = 0; i < 64; i++) s = fmaf(z2[i], fc3_w[i], s);
        out[g] = 1.f / (1.f + expf(-s));
    }
}

// ---------------- host launcher ----------------
extern "C" void kernel_launch(void* const* d_in, const int* in_sizes, int n_in,
                              void* d_out, int out_size) {
    const float *features, *bases1, *comp1, *bias1, *bases2, *comp2, *bias2;
    const float *bases3, *comp3, *bias3, *gate_w, *gate_b;
    const float *fc1_w, *fc1_b, *fc2_w, *fc2_b, *fc3_w, *fc3_b;
    const int *src, *dst, *etype, *n2g;

    if (in_sizes[1] == NE) {
        features = (const float*)d_in[0];
        src      = (const int*)d_in[1];
        dst      = (const int*)d_in[2];
        etype    = (const int*)d_in[3];
        n2g      = (const int*)d_in[4];
        bases1 = (const float*)d_in[5];  comp1 = (const float*)d_in[6];  bias1 = (const float*)d_in[7];
        bases2 = (const float*)d_in[8];  comp2 = (const float*)d_in[9];  bias2 = (const float*)d_in[10];
        bases3 = (const float*)d_in[11]; comp3 = (const float*)d_in[12]; bias3 = (const float*)d_in[13];
        gate_w = (const float*)d_in[14]; gate_b = (const float*)d_in[15];
        fc1_w = (const float*)d_in[16]; fc1_b = (const float*)d_in[17];
        fc2_w = (const float*)d_in[18]; fc2_b = (const float*)d_in[19];
        fc3_w = (const float*)d_in[20]; fc3_b = (const float*)d_in[21];
    } else {
        features = (const float*)d_in[0];
        bases1 = (const float*)d_in[1];  comp1 = (const float*)d_in[2];  bias1 = (const float*)d_in[3];
        bases2 = (const float*)d_in[4];  comp2 = (const float*)d_in[5];  bias2 = (const float*)d_in[6];
        bases3 = (const float*)d_in[7];  comp3 = (const float*)d_in[8];  bias3 = (const float*)d_in[9];
        gate_w = (const float*)d_in[10]; gate_b = (const float*)d_in[11];
        fc1_w = (const float*)d_in[12]; fc1_b = (const float*)d_in[13];
        fc2_w = (const float*)d_in[14]; fc2_b = (const float*)d_in[15];
        fc3_w = (const float*)d_in[16]; fc3_b = (const float*)d_in[17];
        src   = (const int*)d_in[18];
        dst   = (const int*)d_in[19];
        etype = (const int*)d_in[20];
        n2g   = (const int*)d_in[21];
    }
    float* out = (float*)d_out;

    const dim3 gemm_grid(NR, (NN + 127) / 128);          // relation fastest -> A L2 reuse
    const dim3 splitw_grid(64, NR);
    const int split_blocks = (NN * 32 + 255) / 256;      // 6250
    const int node_warp_blocks = NN / 8;                 // 6250
    const int edge_blocks = (NE + 255) / 256;            // 2344
    const int node_blocks = (NN + 255) / 256;            // 196

    // ---- layer 1 front half; GEMM is launch #4 for ncu capture
    k_splitw<<<splitw_grid, 256>>>(bases1, comp1);       // 1
    k_split<<<split_blocks, 256>>>(features);            // 2
    k_hist0<<<node_blocks, 256>>>();                     // 3
    k_gemm_mma<<<gemm_grid, 256>>>();                    // 4  <- profiled
    // ---- CSR build (needed only before first gather)
    k_hist<<<edge_blocks, 256>>>(dst);                   // 5
    k_scan<<<1, 1024>>>();                               // 6
    k_fill<<<edge_blocks, 256>>>(src, dst, etype);       // 7
    // ---- layer 1 -> A2 (fused gather+relu+split)
    k_gather_split<<<node_warp_blocks, 256>>>(bias1);    // 8
    // ---- layer 2
    k_splitw<<<splitw_grid, 256>>>(bases2, comp2);
    k_gemm_mma<<<gemm_grid, 256>>>();
    k_gather_split<<<node_warp_blocks, 256>>>(bias2);
    // ---- layer 3
    k_splitw<<<splitw_grid, 256>>>(bases3, comp3);
    k_gemm_mma<<<gemm_grid, 256>>>();
    k_gather<<<node_warp_blocks, 256>>>(bias3);
    // ---- attention pooling on g_hA
    k_poolinit<<<(NG * DIM + 255) / 256, 256>>>();
    k_gate<<<node_warp_blocks, 256>>>(gate_w, gate_b, n2g);
    k_expsum<<<(NN + 255) / 256, 256>>>(n2g);
    k_readout<<<node_warp_blocks, 256>>>(n2g);
    // ---- MLP head
    k_mlp<<<NG, DIM>>>(fc1_w, fc1_b, fc2_w, fc2_b, fc3_w, fc3_b, out);
}

// round 10
// speedup vs baseline: 1.3253x; 1.0422x over previous
#include <cuda_runtime.h>
#include <cuda_bf16.h>
#include <cstdint>

#define NN 50000
#define NE 600000
#define DIM 128
#define NR 8
#define NB 8
#define NG 256
#define KA 256       // A2: [hi | lo]
#define KW 384       // W2: [Whi ; Whi ; Wlo]

// ---------------- static device scratch ----------------
__device__ __nv_bfloat16 g_A2[(size_t)NN * KA];              // split input, 25.6MB
__device__ __nv_bfloat16 g_W2[NR * DIM * KW];                // split transposed weights
__device__ float g_Hall[(size_t)NN * NR * DIM];              // 204.8 MB fp32
__device__ float g_hA[(size_t)NN * DIM];                     // layer-3 output (pooling input)
__device__ float g_gate[NN];
__device__ float g_gmax[NG];
__device__ float g_gsum[NG];
__device__ float g_read[NG * DIM];
// CSR by dst (rebuilt every launch; edges identical across layers)
__device__ int g_rowptr[NN + 1];
__device__ int g_cursor[NN];
__device__ int g_eidx[NE];                                   // src*8 + etype

// ---------------- PTX helpers (Ampere-class ISA only) ----------------
__device__ __forceinline__ uint32_t smem_u32(const void* p) {
    uint32_t a;
    asm("{ .reg .u64 t; cvta.to.shared.u64 t, %1; cvt.u32.u64 %0, t; }" : "=r"(a) : "l"(p));
    return a;
}
#define CP_ASYNC16(dst, src) \
    asm volatile("cp.async.cg.shared.global [%0], [%1], 16;" :: "r"(dst), "l"(src))
#define CP_COMMIT() asm volatile("cp.async.commit_group;" ::: "memory")
#define CP_WAIT(n)  asm volatile("cp.async.wait_group %0;" :: "n"(n) : "memory")

#define LDMX4(f, addr) asm volatile( \
    "ldmatrix.sync.aligned.m8n8.x4.shared.b16 {%0,%1,%2,%3}, [%4];" \
    : "=r"((f)[0]), "=r"((f)[1]), "=r"((f)[2]), "=r"((f)[3]) : "r"(addr))

#define MMA_BF16(d, a, b0, b1) asm volatile( \
    "mma.sync.aligned.m16n8k16.row.col.f32.bf16.bf16.f32 " \
    "{%0,%1,%2,%3}, {%4,%5,%6,%7}, {%8,%9}, {%0,%1,%2,%3};" \
    : "+f"((d)[0]), "+f"((d)[1]), "+f"((d)[2]), "+f"((d)[3]) \
    : "r"((a)[0]), "r"((a)[1]), "r"((a)[2]), "r"((a)[3]), "r"(b0), "r"(b1))

// ---------------- CSR build ----------------
__global__ void k_hist0() {
    int i = blockIdx.x * 256 + threadIdx.x;
    if (i < NN) g_cursor[i] = 0;
}
__global__ void k_hist(const int* __restrict__ dst) {
    int e = blockIdx.x * 256 + threadIdx.x;
    if (e < NE) atomicAdd(&g_cursor[__ldg(dst + e)], 1);
}
__global__ __launch_bounds__(1024) void k_scan() {
    __shared__ int wsum[32];
    __shared__ int s_carry;
    const int tid = threadIdx.x;
    const int lane = tid & 31, wid = tid >> 5;
    if (tid == 0) s_carry = 0;
    __syncthreads();
    for (int base = 0; base < NN; base += 1024) {
        int i = base + tid;
        int v = (i < NN) ? g_cursor[i] : 0;
        int x = v;
#pragma unroll
        for (int o = 1; o < 32; o <<= 1) {
            int y = __shfl_up_sync(0xffffffffu, x, o);
            if (lane >= o) x += y;
        }
        if (lane == 31) wsum[wid] = x;
        __syncthreads();
        if (wid == 0) {
            int w = (lane < 32) ? wsum[lane] : 0;
#pragma unroll
            for (int o = 1; o < 32; o <<= 1) {
                int y = __shfl_up_sync(0xffffffffu, w, o);
                if (lane >= o) w += y;
            }
            wsum[lane] = w;
        }
        __syncthreads();
        int incl = x + (wid > 0 ? wsum[wid - 1] : 0) + s_carry;
        int excl = incl - v;
        if (i < NN) { g_rowptr[i] = excl; g_cursor[i] = excl; }
        if (i == NN - 1) g_rowptr[NN] = incl;
        __syncthreads();
        if (tid == 1023) s_carry = incl;
        __syncthreads();
    }
}
__global__ void k_fill(const int* __restrict__ src, const int* __restrict__ dst,
                       const int* __restrict__ et) {
    int e = blockIdx.x * 256 + threadIdx.x;
    if (e >= NE) return;
    int d = __ldg(dst + e);
    int pos = atomicAdd(&g_cursor[d], 1);
    g_eidx[pos] = __ldg(src + e) * NR + __ldg(et + e);
}

// ---------------- split weights ----------------
__global__ void k_splitw(const float* __restrict__ bases, const float* __restrict__ comp) {
    int r = blockIdx.y;
    int t = blockIdx.x * 256 + threadIdx.x;
    if (t >= DIM * DIM) return;
    int k = t >> 7, n = t & 127;
    float s = 0.f;
#pragma unroll
    for (int b = 0; b < NB; b++)
        s = fmaf(comp[r * NB + b], bases[((size_t)b * DIM + k) * DIM + n], s);
    __nv_bfloat16 hi = __float2bfloat16(s);
    __nv_bfloat16 lo = __float2bfloat16(s - __bfloat162float(hi));
    __nv_bfloat16* w = g_W2 + ((size_t)r * DIM + n) * KW;
    w[k] = hi; w[128 + k] = hi; w[256 + k] = lo;
}

// ---------------- split activations (features only): A2[n] = [hi | lo] ----------------
__global__ void k_split(const float* __restrict__ A) {
    size_t idx = (size_t)blockIdx.x * blockDim.x + threadIdx.x;   // NN*32
    if (idx >= (size_t)NN * 32) return;
    size_t n = idx >> 5;
    int c4 = (int)(idx & 31);
    float4 v = ((const float4*)(A + n * DIM))[c4];
    __nv_bfloat16 h[4], l[4];
    float f[4] = {v.x, v.y, v.z, v.w};
#pragma unroll
    for (int i = 0; i < 4; i++) {
        h[i] = __float2bfloat16(f[i]);
        l[i] = __float2bfloat16(f[i] - __bfloat162float(h[i]));
    }
    __nv_bfloat16* a2 = g_A2 + n * KA + c4 * 4;
    *(uint2*)(a2)       = *(uint2*)h;
    *(uint2*)(a2 + 128) = *(uint2*)l;
}

// ---------------- HMMA GEMM: BK=64, DOUBLE-buffered (dynamic smem), 2 CTA/SM ----------------
// grid = (NR, mtiles). Stage size: sA 18432B + sB 18432B = 36864B; 2 stages = 73728B.
#define STAGE_BYTES (128 * 72 * 2)
__global__ __launch_bounds__(256, 2) void k_gemm_mma() {
    constexpr int SP = 72;                                // bf16 per smem row
    extern __shared__ __align__(16) char dynsmem[];

    const int tid = threadIdx.x;
    const int wid = tid >> 5, lane = tid & 31;
    const int r = blockIdx.x;                             // relation = fast index
    const int m0 = blockIdx.y * 128;
    const int wm = (wid & 3) * 32;
    const int wn = (wid >> 2) * 64;

    const __nv_bfloat16* __restrict__ Ag = g_A2;
    const __nv_bfloat16* __restrict__ Bg = g_W2 + (size_t)r * DIM * KW;

    const int a_off[6] = {0, 64, 128, 192, 0, 64};        // hi hi lo lo hi hi

    float acc[2][8][4];
#pragma unroll
    for (int mi = 0; mi < 2; mi++)
#pragma unroll
        for (int ni = 0; ni < 8; ni++)
#pragma unroll
            for (int q = 0; q < 4; q++) acc[mi][ni][q] = 0.f;

    const uint32_t smem_base = smem_u32(dynsmem);
    const int lrow = (lane & 15);
    const int lcol = (lane & 16) ? 8 : 0;

    // staging coords: each thread copies 4 x 16B for A and 4 x 16B for B
    auto stage = [&](int kc, int buf) {
        uint32_t sA_b = smem_base + buf * 2 * STAGE_BYTES;
        uint32_t sB_b = sA_b + STAGE_BYTES;
#pragma unroll
        for (int i = 0; i < 4; i++) {
            int id = tid + i * 256;
            int row = id >> 3, seg = id & 7;
            int gr = m0 + row; if (gr >= NN) gr = NN - 1;
            CP_ASYNC16(sA_b + (row * SP + seg * 8) * 2,
                       Ag + (size_t)gr * KA + a_off[kc] + seg * 8);
            CP_ASYNC16(sB_b + (row * SP + seg * 8) * 2,
                       Bg + (size_t)row * KW + kc * 64 + seg * 8);
        }
        CP_COMMIT();
    };

    stage(0, 0);

    for (int kc = 0; kc < 6; kc++) {
        const int buf = kc & 1;
        if (kc + 1 < 6) { stage(kc + 1, buf ^ 1); CP_WAIT(1); }
        else           { CP_WAIT(0); }
        __syncthreads();

        const uint32_t sA_b = smem_base + buf * 2 * STAGE_BYTES;
        const uint32_t sB_b = sA_b + STAGE_BYTES;
#pragma unroll
        for (int ks = 0; ks < 4; ks++) {
            const int k0 = ks * 16;
            uint32_t aF[2][4], bF[4][4];
#pragma unroll
            for (int mi = 0; mi < 2; mi++)
                LDMX4(aF[mi], sA_b + ((wm + mi * 16 + lrow) * SP + k0 + lcol) * 2);
#pragma unroll
            for (int g = 0; g < 4; g++)
                LDMX4(bF[g], sB_b + ((wn + g * 16 + lrow) * SP + k0 + lcol) * 2);
#pragma unroll
            for (int mi = 0; mi < 2; mi++)
#pragma unroll
                for (int ni = 0; ni < 8; ni++) {
                    uint32_t b0 = bF[ni >> 1][(ni & 1)];
                    uint32_t b1 = bF[ni >> 1][(ni & 1) + 2];
                    MMA_BF16(acc[mi][ni], aF[mi], b0, b1);
                }
        }
        __syncthreads();   // all warps done reading buf before it's restaged (kc+2)
    }

#pragma unroll
    for (int mi = 0; mi < 2; mi++) {
        int row0 = m0 + wm + mi * 16 + (lane >> 2);
#pragma unroll
        for (int half = 0; half < 2; half++) {
            int gr = row0 + half * 8;
            if (gr < NN) {
                float* base = g_Hall + ((size_t)gr * NR + r) * DIM + wn + (lane & 3) * 2;
#pragma unroll
                for (int ni = 0; ni < 8; ni++)
                    *(float2*)(base + ni * 8) =
                        make_float2(acc[mi][ni][half * 2], acc[mi][ni][half * 2 + 1]);
            }
        }
    }
}

// ---------------- fused gather + relu + split -> A2 (layer boundaries) ----------------
__global__ void k_gather_split(const float* __restrict__ bias) {
    int n = blockIdx.x * 8 + (threadIdx.x >> 5);
    if (n >= NN) return;
    int lane = threadIdx.x & 31;
    float4 acc = ((const float4*)bias)[lane];
    int beg = __ldg(&g_rowptr[n]), end = __ldg(&g_rowptr[n + 1]);
    for (int e = beg; e < end; e++) {
        int p = __ldg(&g_eidx[e]);
        float4 v = ((const float4*)(g_Hall + (size_t)p * DIM))[lane];
        acc.x += v.x; acc.y += v.y; acc.z += v.z; acc.w += v.w;
    }
    float f[4] = {fmaxf(acc.x, 0.f), fmaxf(acc.y, 0.f), fmaxf(acc.z, 0.f), fmaxf(acc.w, 0.f)};
    __nv_bfloat16 h[4], l[4];
#pragma unroll
    for (int i = 0; i < 4; i++) {
        h[i] = __float2bfloat16(f[i]);
        l[i] = __float2bfloat16(f[i] - __bfloat162float(h[i]));
    }
    __nv_bfloat16* a2 = g_A2 + (size_t)n * KA + lane * 4;
    *(uint2*)(a2)       = *(uint2*)h;
    *(uint2*)(a2 + 128) = *(uint2*)l;
}

// ---------------- final gather (layer 3, fp32, no relu) ----------------
__global__ void k_gather(const float* __restrict__ bias) {
    int n = blockIdx.x * 8 + (threadIdx.x >> 5);
    if (n >= NN) return;
    int lane = threadIdx.x & 31;
    float4 acc = ((const float4*)bias)[lane];
    int beg = __ldg(&g_rowptr[n]), end = __ldg(&g_rowptr[n + 1]);
    for (int e = beg; e < end; e++) {
        int p = __ldg(&g_eidx[e]);
        float4 v = ((const float4*)(g_Hall + (size_t)p * DIM))[lane];
        acc.x += v.x; acc.y += v.y; acc.z += v.z; acc.w += v.w;
    }
    ((float4*)(g_hA + (size_t)n * DIM))[lane] = acc;
}

// ---------------- pooling ----------------
__global__ void k_poolinit() {
    int idx = blockIdx.x * blockDim.x + threadIdx.x;
    if (idx < NG) { g_gmax[idx] = -__int_as_float(0x7f800000); g_gsum[idx] = 0.f; }
    if (idx < NG * DIM) g_read[idx] = 0.f;
}

__global__ void k_gate(const float* __restrict__ gw, const float* __restrict__ gb,
                       const int* __restrict__ n2g) {
    int n = blockIdx.x * 8 + (threadIdx.x >> 5);
    if (n >= NN) return;
    int lane = threadIdx.x & 31;
    float4 hv = ((const float4*)(g_hA + (size_t)n * DIM))[lane];
    float4 wv = ((const float4*)gw)[lane];
    float s = hv.x * wv.x + hv.y * wv.y + hv.z * wv.z + hv.w * wv.w;
#pragma unroll
    for (int o = 16; o; o >>= 1) s += __shfl_xor_sync(0xffffffffu, s, o);
    if (lane == 0) {
        s += gb[0];
        g_gate[n] = s;
        int g = n2g[n];
        int* ia = (int*)&g_gmax[g];
        int old = *ia;
        while (__int_as_float(old) < s) {
            int prev = atomicCAS(ia, old, __float_as_int(s));
            if (prev == old) break;
            old = prev;
        }
    }
}

__global__ void k_expsum(const int* __restrict__ n2g) {
    int n = blockIdx.x * blockDim.x + threadIdx.x;
    if (n >= NN) return;
    int g = n2g[n];
    float e = expf(g_gate[n] - g_gmax[g]);
    g_gate[n] = e;
    atomicAdd(&g_gsum[g], e);
}

__global__ void k_readout(const int* __restrict__ n2g) {
    int n = blockIdx.x * 8 + (threadIdx.x >> 5);
    if (n >= NN) return;
    int lane = threadIdx.x & 31;
    int g = n2g[n];
    float w = g_gate[n] / g_gsum[g];
    float4 hv = ((const float4*)(g_hA + (size_t)n * DIM))[lane];
    float* o = g_read + g * DIM + lane * 4;
    asm volatile("red.global.add.v4.f32 [%0], {%1,%2,%3,%4};"
                 :: "l"(o), "f"(hv.x * w), "f"(hv.y * w), "f"(hv.z * w), "f"(hv.w * w)
                 : "memory");
}

// ---------------- MLP head ----------------
__global__ void k_mlp(const float* __restrict__ fc1_w, const float* __restrict__ fc1_b,
                      const float* __restrict__ fc2_w, const float* __restrict__ fc2_b,
                      const float* __restrict__ fc3_w, const float* __restrict__ fc3_b,
                      float* __restrict__ out) {
    int g = blockIdx.x;
    int t = threadIdx.x;
    __shared__ float r[DIM];
    __shared__ float z1[100];
    __shared__ float z2[64];
    r[t] = g_read[g * DIM + t];
    __syncthreads();
    if (t < 100) {
        float s = fc1_b[t];
        for (int i = 0; i < DIM; i++) s = fmaf(r[i], fc1_w[i * 100 + t], s);
        z1[t] = fmaxf(s, 0.f);
    }
    __syncthreads();
    if (t < 64) {
        float s = fc2_b[t];
        for (int i = 0; i < 100; i++) s = fmaf(z1[i], fc2_w[i * 64 + t], s);
        z2[t] = fmaxf(s, 0.f);
    }
    __syncthreads();
    if (t == 0) {
        float s = fc3_b[0];
        for (int i = 0; i < 64; i++) s = fmaf(z2[i], fc3_w[i], s);
        out[g] = 1.f / (1.f + expf(-s));
    }
}

// ---------------- host launcher ----------------
extern "C" void kernel_launch(void* const* d_in, const int* in_sizes, int n_in,
                              void* d_out, int out_size) {
    const float *features, *bases1, *comp1, *bias1, *bases2, *comp2, *bias2;
    const float *bases3, *comp3, *bias3, *gate_w, *gate_b;
    const float *fc1_w, *fc1_b, *fc2_w, *fc2_b, *fc3_w, *fc3_b;
    const int *src, *dst, *etype, *n2g;

    if (in_sizes[1] == NE) {
        features = (const float*)d_in[0];
        src      = (const int*)d_in[1];
        dst      = (const int*)d_in[2];
        etype    = (const int*)d_in[3];
        n2g      = (const int*)d_in[4];
        bases1 = (const float*)d_in[5];  comp1 = (const float*)d_in[6];  bias1 = (const float*)d_in[7];
        bases2 = (const float*)d_in[8];  comp2 = (const float*)d_in[9];  bias2 = (const float*)d_in[10];
        bases3 = (const float*)d_in[11]; comp3 = (const float*)d_in[12]; bias3 = (const float*)d_in[13];
        gate_w = (const float*)d_in[14]; gate_b = (const float*)d_in[15];
        fc1_w = (const float*)d_in[16]; fc1_b = (const float*)d_in[17];
        fc2_w = (const float*)d_in[18]; fc2_b = (const float*)d_in[19];
        fc3_w = (const float*)d_in[20]; fc3_b = (const float*)d_in[21];
    } else {
        features = (const float*)d_in[0];
        bases1 = (const float*)d_in[1];  comp1 = (const float*)d_in[2];  bias1 = (const float*)d_in[3];
        bases2 = (const float*)d_in[4];  comp2 = (const float*)d_in[5];  bias2 = (const float*)d_in[6];
        bases3 = (const float*)d_in[7];  comp3 = (const float*)d_in[8];  bias3 = (const float*)d_in[9];
        gate_w = (const float*)d_in[10]; gate_b = (const float*)d_in[11];
        fc1_w = (const float*)d_in[12]; fc1_b = (const float*)d_in[13];
        fc2_w = (const float*)d_in[14]; fc2_b = (const float*)d_in[15];
        fc3_w = (const float*)d_in[16]; fc3_b = (const float*)d_in[17];
        src   = (const int*)d_in[18];
        dst   = (const int*)d_in[19];
        etype = (const int*)d_in[20];
        n2g   = (const int*)d_in[21];
    }
    float* out = (float*)d_out;

    const dim3 gemm_grid(NR, (NN + 127) / 128);          // relation fastest -> A L2 reuse
    const dim3 splitw_grid(64, NR);
    const int split_blocks = (NN * 32 + 255) / 256;      // 6250
    const int node_warp_blocks = NN / 8;                 // 6250
    const int edge_blocks = (NE + 255) / 256;            // 2344
    const int node_blocks = (NN + 255) / 256;            // 196
    const int gemm_smem = 2 * 2 * STAGE_BYTES;           // 73728 B

    static int smem_set = 0;
    if (!smem_set) {
        cudaFuncSetAttribute(k_gemm_mma, cudaFuncAttributeMaxDynamicSharedMemorySize, gemm_smem);
        smem_set = 1;
    }

    // ---- layer 1 front half; GEMM is launch #4 for ncu capture
    k_splitw<<<splitw_grid, 256>>>(bases1, comp1);       // 1
    k_split<<<split_blocks, 256>>>(features);            // 2
    k_hist0<<<node_blocks, 256>>>();                     // 3
    k_gemm_mma<<<gemm_grid, 256, gemm_smem>>>();         // 4  <- profiled
    // ---- CSR build (needed only before first gather)
    k_hist<<<edge_blocks, 256>>>(dst);                   // 5
    k_scan<<<1, 1024>>>();                               // 6
    k_fill<<<edge_blocks, 256>>>(src, dst, etype);       // 7
    // ---- layer 1 -> A2 (fused gather+relu+split)
    k_gather_split<<<node_warp_blocks, 256>>>(bias1);    // 8
    // ---- layer 2
    k_splitw<<<splitw_grid, 256>>>(bases2, comp2);
    k_gemm_mma<<<gemm_grid, 256, gemm_smem>>>();
    k_gather_split<<<node_warp_blocks, 256>>>(bias2);
    // ---- layer 3
    k_splitw<<<splitw_grid, 256>>>(bases3, comp3);
    k_gemm_mma<<<gemm_grid, 256, gemm_smem>>>();
    k_gather<<<node_warp_blocks, 256>>>(bias3);
    // ---- attention pooling on g_hA
    k_poolinit<<<(NG * DIM + 255) / 256, 256>>>();
    k_gate<<<node_warp_blocks, 256>>>(gate_w, gate_b, n2g);
    k_expsum<<<(NN + 255) / 256, 256>>>(n2g);
    k_readout<<<node_warp_blocks, 256>>>(n2g);
    // ---- MLP head
    k_mlp<<<NG, DIM>>>(fc1_w, fc1_b, fc2_w, fc2_b, fc3_w, fc3_b, out);
}

// round 12
// speedup vs baseline: 1.3292x; 1.0029x over previous
#include <cuda_runtime.h>
#include <cuda_bf16.h>
#include <cstdint>

#define NN 50000
#define NE 600000
#define DIM 128
#define NR 8
#define NB 8
#define NG 256
#define KA 256       // A2: [hi | lo]
#define KW 384       // W2: [Whi ; Whi ; Wlo]

// ---------------- static device scratch ----------------
__device__ __nv_bfloat16 g_A2[(size_t)NN * KA];              // split input, 25.6MB
__device__ __nv_bfloat16 g_W2[NR * DIM * KW];                // split transposed weights
__device__ float g_Hall[(size_t)NN * NR * DIM];              // 204.8 MB fp32
__device__ float g_hA[(size_t)NN * DIM];                     // layer-3 output (pooling input)
__device__ float g_gate[NN];
__device__ float g_gmax[NG];
__device__ float g_gsum[NG];
__device__ float g_read[NG * DIM];
// CSR by dst (rebuilt every launch; edges identical across layers)
__device__ int g_rowptr[NN + 1];
__device__ int g_cursor[NN];
__device__ int g_eidx[NE];                                   // src*8 + etype

// ---------------- PTX helpers (Ampere-class ISA only) ----------------
__device__ __forceinline__ uint32_t smem_u32(const void* p) {
    uint32_t a;
    asm("{ .reg .u64 t; cvta.to.shared.u64 t, %1; cvt.u32.u64 %0, t; }" : "=r"(a) : "l"(p));
    return a;
}
#define CP_ASYNC16(dst, src) \
    asm volatile("cp.async.cg.shared.global [%0], [%1], 16;" :: "r"(dst), "l"(src))
#define CP_COMMIT() asm volatile("cp.async.commit_group;" ::: "memory")
#define CP_WAIT(n)  asm volatile("cp.async.wait_group %0;" :: "n"(n) : "memory")

#define LDMX4(f, addr) asm volatile( \
    "ldmatrix.sync.aligned.m8n8.x4.shared.b16 {%0,%1,%2,%3}, [%4];" \
    : "=r"((f)[0]), "=r"((f)[1]), "=r"((f)[2]), "=r"((f)[3]) : "r"(addr))

#define MMA_BF16(d, a, b0, b1) asm volatile( \
    "mma.sync.aligned.m16n8k16.row.col.f32.bf16.bf16.f32 " \
    "{%0,%1,%2,%3}, {%4,%5,%6,%7}, {%8,%9}, {%0,%1,%2,%3};" \
    : "+f"((d)[0]), "+f"((d)[1]), "+f"((d)[2]), "+f"((d)[3]) \
    : "r"((a)[0]), "r"((a)[1]), "r"((a)[2]), "r"((a)[3]), "r"(b0), "r"(b1))

// ---------------- CSR build ----------------
__global__ void k_hist0() {
    int i = blockIdx.x * 256 + threadIdx.x;
    if (i < NN) g_cursor[i] = 0;
}
__global__ void k_hist(const int* __restrict__ dst) {
    int e = blockIdx.x * 256 + threadIdx.x;
    if (e < NE) atomicAdd(&g_cursor[__ldg(dst + e)], 1);
}
__global__ __launch_bounds__(1024) void k_scan() {
    __shared__ int wsum[32];
    __shared__ int s_carry;
    const int tid = threadIdx.x;
    const int lane = tid & 31, wid = tid >> 5;
    if (tid == 0) s_carry = 0;
    __syncthreads();
    for (int base = 0; base < NN; base += 1024) {
        int i = base + tid;
        int v = (i < NN) ? g_cursor[i] : 0;
        int x = v;
#pragma unroll
        for (int o = 1; o < 32; o <<= 1) {
            int y = __shfl_up_sync(0xffffffffu, x, o);
            if (lane >= o) x += y;
        }
        if (lane == 31) wsum[wid] = x;
        __syncthreads();
        if (wid == 0) {
            int w = (lane < 32) ? wsum[lane] : 0;
#pragma unroll
            for (int o = 1; o < 32; o <<= 1) {
                int y = __shfl_up_sync(0xffffffffu, w, o);
                if (lane >= o) w += y;
            }
            wsum[lane] = w;
        }
        __syncthreads();
        int incl = x + (wid > 0 ? wsum[wid - 1] : 0) + s_carry;
        int excl = incl - v;
        if (i < NN) { g_rowptr[i] = excl; g_cursor[i] = excl; }
        if (i == NN - 1) g_rowptr[NN] = incl;
        __syncthreads();
        if (tid == 1023) s_carry = incl;
        __syncthreads();
    }
}
__global__ void k_fill(const int* __restrict__ src, const int* __restrict__ dst,
                       const int* __restrict__ et) {
    int e = blockIdx.x * 256 + threadIdx.x;
    if (e >= NE) return;
    int d = __ldg(dst + e);
    int pos = atomicAdd(&g_cursor[d], 1);
    g_eidx[pos] = __ldg(src + e) * NR + __ldg(et + e);
}

// ---------------- split weights ----------------
__global__ void k_splitw(const float* __restrict__ bases, const float* __restrict__ comp) {
    int r = blockIdx.y;
    int t = blockIdx.x * 256 + threadIdx.x;
    if (t >= DIM * DIM) return;
    int k = t >> 7, n = t & 127;
    float s = 0.f;
#pragma unroll
    for (int b = 0; b < NB; b++)
        s = fmaf(comp[r * NB + b], bases[((size_t)b * DIM + k) * DIM + n], s);
    __nv_bfloat16 hi = __float2bfloat16(s);
    __nv_bfloat16 lo = __float2bfloat16(s - __bfloat162float(hi));
    __nv_bfloat16* w = g_W2 + ((size_t)r * DIM + n) * KW;
    w[k] = hi; w[128 + k] = hi; w[256 + k] = lo;
}

// ---------------- split activations (features only): A2[n] = [hi | lo] ----------------
__global__ void k_split(const float* __restrict__ A) {
    size_t idx = (size_t)blockIdx.x * blockDim.x + threadIdx.x;   // NN*32
    if (idx >= (size_t)NN * 32) return;
    size_t n = idx >> 5;
    int c4 = (int)(idx & 31);
    float4 v = ((const float4*)(A + n * DIM))[c4];
    __nv_bfloat16 h[4], l[4];
    float f[4] = {v.x, v.y, v.z, v.w};
#pragma unroll
    for (int i = 0; i < 4; i++) {
        h[i] = __float2bfloat16(f[i]);
        l[i] = __float2bfloat16(f[i] - __bfloat162float(h[i]));
    }
    __nv_bfloat16* a2 = g_A2 + n * KA + c4 * 4;
    *(uint2*)(a2)       = *(uint2*)h;
    *(uint2*)(a2 + 128) = *(uint2*)l;
}

// ---------------- HMMA GEMM: BK=64, TRIPLE-buffered (dynamic smem), 2 CTA/SM ----------------
// grid = (NR, mtiles). Stage: sA 18432B + sB 18432B = 36864B; 3 stages = 110592B.
#define MAT_BYTES   (128 * 72 * 2)
#define STAGE_FULL  (2 * MAT_BYTES)
__global__ __launch_bounds__(256, 2) void k_gemm_mma() {
    constexpr int SP = 72;                                // bf16 per smem row
    extern __shared__ __align__(16) char dynsmem[];

    const int tid = threadIdx.x;
    const int wid = tid >> 5, lane = tid & 31;
    const int r = blockIdx.x;                             // relation = fast index
    const int m0 = blockIdx.y * 128;
    const int wm = (wid & 3) * 32;
    const int wn = (wid >> 2) * 64;

    const __nv_bfloat16* __restrict__ Ag = g_A2;
    const __nv_bfloat16* __restrict__ Bg = g_W2 + (size_t)r * DIM * KW;

    const int a_off[6] = {0, 64, 128, 192, 0, 64};        // hi hi lo lo hi hi

    float acc[2][8][4];
#pragma unroll
    for (int mi = 0; mi < 2; mi++)
#pragma unroll
        for (int ni = 0; ni < 8; ni++)
#pragma unroll
            for (int q = 0; q < 4; q++) acc[mi][ni][q] = 0.f;

    const uint32_t smem_base = smem_u32(dynsmem);
    const int lrow = (lane & 15);
    const int lcol = (lane & 16) ? 8 : 0;

    auto stage = [&](int kc, int buf) {
        uint32_t sA_b = smem_base + buf * STAGE_FULL;
        uint32_t sB_b = sA_b + MAT_BYTES;
#pragma unroll
        for (int i = 0; i < 4; i++) {
            int id = tid + i * 256;
            int row = id >> 3, seg = id & 7;
            int gr = m0 + row; if (gr >= NN) gr = NN - 1;
            CP_ASYNC16(sA_b + (row * SP + seg * 8) * 2,
                       Ag + (size_t)gr * KA + a_off[kc] + seg * 8);
            CP_ASYNC16(sB_b + (row * SP + seg * 8) * 2,
                       Bg + (size_t)row * KW + kc * 64 + seg * 8);
        }
        CP_COMMIT();
    };

    stage(0, 0);
    stage(1, 1);

    for (int kc = 0; kc < 6; kc++) {
        const int buf = kc % 3;
        if (kc < 5) CP_WAIT(1); else CP_WAIT(0);
        __syncthreads();
        if (kc + 2 < 6) stage(kc + 2, (kc + 2) % 3);      // overwrites buf of kc-1 (safe)

        const uint32_t sA_b = smem_base + buf * STAGE_FULL;
        const uint32_t sB_b = sA_b + MAT_BYTES;
#pragma unroll
        for (int ks = 0; ks < 4; ks++) {
            const int k0 = ks * 16;
            uint32_t aF[2][4], bF[4][4];
#pragma unroll
            for (int mi = 0; mi < 2; mi++)
                LDMX4(aF[mi], sA_b + ((wm + mi * 16 + lrow) * SP + k0 + lcol) * 2);
#pragma unroll
            for (int g = 0; g < 4; g++)
                LDMX4(bF[g], sB_b + ((wn + g * 16 + lrow) * SP + k0 + lcol) * 2);
#pragma unroll
            for (int mi = 0; mi < 2; mi++)
#pragma unroll
                for (int ni = 0; ni < 8; ni++) {
                    uint32_t b0 = bF[ni >> 1][(ni & 1)];
                    uint32_t b1 = bF[ni >> 1][(ni & 1) + 2];
                    MMA_BF16(acc[mi][ni], aF[mi], b0, b1);
                }
        }
        __syncthreads();   // all warps done reading buf before it's restaged (kc+3)
    }

#pragma unroll
    for (int mi = 0; mi < 2; mi++) {
        int row0 = m0 + wm + mi * 16 + (lane >> 2);
#pragma unroll
        for (int half = 0; half < 2; half++) {
            int gr = row0 + half * 8;
            if (gr < NN) {
                float* base = g_Hall + ((size_t)gr * NR + r) * DIM + wn + (lane & 3) * 2;
#pragma unroll
                for (int ni = 0; ni < 8; ni++)
                    *(float2*)(base + ni * 8) =
                        make_float2(acc[mi][ni][half * 2], acc[mi][ni][half * 2 + 1]);
            }
        }
    }
}

// ---------------- fused gather + relu + split -> A2 (layer boundaries) ----------------
__global__ void k_gather_split(const float* __restrict__ bias) {
    int n = blockIdx.x * 8 + (threadIdx.x >> 5);
    if (n >= NN) return;
    int lane = threadIdx.x & 31;
    float4 acc = ((const float4*)bias)[lane];
    float4 acc2 = make_float4(0.f, 0.f, 0.f, 0.f);
    int beg = __ldg(&g_rowptr[n]), end = __ldg(&g_rowptr[n + 1]);
    int e = beg;
    for (; e + 1 < end; e += 2) {
        int p0 = __ldg(&g_eidx[e]);
        int p1 = __ldg(&g_eidx[e + 1]);
        float4 v0 = ((const float4*)(g_Hall + (size_t)p0 * DIM))[lane];
        float4 v1 = ((const float4*)(g_Hall + (size_t)p1 * DIM))[lane];
        acc.x += v0.x; acc.y += v0.y; acc.z += v0.z; acc.w += v0.w;
        acc2.x += v1.x; acc2.y += v1.y; acc2.z += v1.z; acc2.w += v1.w;
    }
    if (e < end) {
        int p = __ldg(&g_eidx[e]);
        float4 v = ((const float4*)(g_Hall + (size_t)p * DIM))[lane];
        acc.x += v.x; acc.y += v.y; acc.z += v.z; acc.w += v.w;
    }
    acc.x += acc2.x; acc.y += acc2.y; acc.z += acc2.z; acc.w += acc2.w;
    float f[4] = {fmaxf(acc.x, 0.f), fmaxf(acc.y, 0.f), fmaxf(acc.z, 0.f), fmaxf(acc.w, 0.f)};
    __nv_bfloat16 h[4], l[4];
#pragma unroll
    for (int i = 0; i < 4; i++) {
        h[i] = __float2bfloat16(f[i]);
        l[i] = __float2bfloat16(f[i] - __bfloat162float(h[i]));
    }
    __nv_bfloat16* a2 = g_A2 + (size_t)n * KA + lane * 4;
    *(uint2*)(a2)       = *(uint2*)h;
    *(uint2*)(a2 + 128) = *(uint2*)l;
}

// ---------------- final gather (layer 3, fp32, no relu) ----------------
__global__ void k_gather(const float* __restrict__ bias) {
    int n = blockIdx.x * 8 + (threadIdx.x >> 5);
    if (n >= NN) return;
    int lane = threadIdx.x & 31;
    float4 acc = ((const float4*)bias)[lane];
    float4 acc2 = make_float4(0.f, 0.f, 0.f, 0.f);
    int beg = __ldg(&g_rowptr[n]), end = __ldg(&g_rowptr[n + 1]);
    int e = beg;
    for (; e + 1 < end; e += 2) {
        int p0 = __ldg(&g_eidx[e]);
        int p1 = __ldg(&g_eidx[e + 1]);
        float4 v0 = ((const float4*)(g_Hall + (size_t)p0 * DIM))[lane];
        float4 v1 = ((const float4*)(g_Hall + (size_t)p1 * DIM))[lane];
        acc.x += v0.x; acc.y += v0.y; acc.z += v0.z; acc.w += v0.w;
        acc2.x += v1.x; acc2.y += v1.y; acc2.z += v1.z; acc2.w += v1.w;
    }
    if (e < end) {
        int p = __ldg(&g_eidx[e]);
        float4 v = ((const float4*)(g_Hall + (size_t)p * DIM))[lane];
        acc.x += v.x; acc.y += v.y; acc.z += v.z; acc.w += v.w;
    }
    acc.x += acc2.x; acc.y += acc2.y; acc.z += acc2.z; acc.w += acc2.w;
    ((float4*)(g_hA + (size_t)n * DIM))[lane] = acc;
}

// ---------------- pooling ----------------
__global__ void k_poolinit() {
    int idx = blockIdx.x * blockDim.x + threadIdx.x;
    if (idx < NG) { g_gmax[idx] = -__int_as_float(0x7f800000); g_gsum[idx] = 0.f; }
    if (idx < NG * DIM) g_read[idx] = 0.f;
}

__global__ void k_gate(const float* __restrict__ gw, const float* __restrict__ gb,
                       const int* __restrict__ n2g) {
    int n = blockIdx.x * 8 + (threadIdx.x >> 5);
    if (n >= NN) return;
    int lane = threadIdx.x & 31;
    float4 hv = ((const float4*)(g_hA + (size_t)n * DIM))[lane];
    float4 wv = ((const float4*)gw)[lane];
    float s = hv.x * wv.x + hv.y * wv.y + hv.z * wv.z + hv.w * wv.w;
#pragma unroll
    for (int o = 16; o; o >>= 1) s += __shfl_xor_sync(0xffffffffu, s, o);
    if (lane == 0) {
        s += gb[0];
        g_gate[n] = s;
        int g = n2g[n];
        int* ia = (int*)&g_gmax[g];
        int old = *ia;
        while (__int_as_float(old) < s) {
            int prev = atomicCAS(ia, old, __float_as_int(s));
            if (prev == old) break;
            old = prev;
        }
    }
}

__global__ void k_expsum(const int* __restrict__ n2g) {
    int n = blockIdx.x * blockDim.x + threadIdx.x;
    if (n >= NN) return;
    int g = n2g[n];
    float e = expf(g_gate[n] - g_gmax[g]);
    g_gate[n] = e;
    atomicAdd(&g_gsum[g], e);
}

__global__ void k_readout(const int* __restrict__ n2g) {
    int n = blockIdx.x * 8 + (threadIdx.x >> 5);
    if (n >= NN) return;
    int lane = threadIdx.x & 31;
    int g = n2g[n];
    float w = g_gate[n] / g_gsum[g];
    float4 hv = ((const float4*)(g_hA + (size_t)n * DIM))[lane];
    float* o = g_read + g * DIM + lane * 4;
    asm volatile("red.global.add.v4.f32 [%0], {%1,%2,%3,%4};"
                 :: "l"(o), "f"(hv.x * w), "f"(hv.y * w), "f"(hv.z * w), "f"(hv.w * w)
                 : "memory");
}

// ---------------- MLP head ----------------
__global__ void k_mlp(const float* __restrict__ fc1_w, const float* __restrict__ fc1_b,
                      const float* __restrict__ fc2_w, const float* __restrict__ fc2_b,
                      const float* __restrict__ fc3_w, const float* __restrict__ fc3_b,
                      float* __restrict__ out) {
    int g = blockIdx.x;
    int t = threadIdx.x;
    __shared__ float r[DIM];
    __shared__ float z1[100];
    __shared__ float z2[64];
    r[t] = g_read[g * DIM + t];
    __syncthreads();
    if (t < 100) {
        float s = fc1_b[t];
        for (int i = 0; i < DIM; i++) s = fmaf(r[i], fc1_w[i * 100 + t], s);
        z1[t] = fmaxf(s, 0.f);
    }
    __syncthreads();
    if (t < 64) {
        float s = fc2_b[t];
        for (int i = 0; i < 100; i++) s = fmaf(z1[i], fc2_w[i * 64 + t], s);
        z2[t] = fmaxf(s, 0.f);
    }
    __syncthreads();
    if (t == 0) {
        float s = fc3_b[0];
        for (int i = 0; i < 64; i++) s = fmaf(z2[i], fc3_w[i], s);
        out[g] = 1.f / (1.f + expf(-s));
    }
}

// ---------------- host launcher ----------------
extern "C" void kernel_launch(void* const* d_in, const int* in_sizes, int n_in,
                              void* d_out, int out_size) {
    const float *features, *bases1, *comp1, *bias1, *bases2, *comp2, *bias2;
    const float *bases3, *comp3, *bias3, *gate_w, *gate_b;
    const float *fc1_w, *fc1_b, *fc2_w, *fc2_b, *fc3_w, *fc3_b;
    const int *src, *dst, *etype, *n2g;

    if (in_sizes[1] == NE) {
        features = (const float*)d_in[0];
        src      = (const int*)d_in[1];
        dst      = (const int*)d_in[2];
        etype    = (const int*)d_in[3];
        n2g      = (const int*)d_in[4];
        bases1 = (const float*)d_in[5];  comp1 = (const float*)d_in[6];  bias1 = (const float*)d_in[7];
        bases2 = (const float*)d_in[8];  comp2 = (const float*)d_in[9];  bias2 = (const float*)d_in[10];
        bases3 = (const float*)d_in[11]; comp3 = (const float*)d_in[12]; bias3 = (const float*)d_in[13];
        gate_w = (const float*)d_in[14]; gate_b = (const float*)d_in[15];
        fc1_w = (const float*)d_in[16]; fc1_b = (const float*)d_in[17];
        fc2_w = (const float*)d_in[18]; fc2_b = (const float*)d_in[19];
        fc3_w = (const float*)d_in[20]; fc3_b = (const float*)d_in[21];
    } else {
        features = (const float*)d_in[0];
        bases1 = (const float*)d_in[1];  comp1 = (const float*)d_in[2];  bias1 = (const float*)d_in[3];
        bases2 = (const float*)d_in[4];  comp2 = (const float*)d_in[5];  bias2 = (const float*)d_in[6];
        bases3 = (const float*)d_in[7];  comp3 = (const float*)d_in[8];  bias3 = (const float*)d_in[9];
        gate_w = (const float*)d_in[10]; gate_b = (const float*)d_in[11];
        fc1_w = (const float*)d_in[12]; fc1_b = (const float*)d_in[13];
        fc2_w = (const float*)d_in[14]; fc2_b = (const float*)d_in[15];
        fc3_w = (const float*)d_in[16]; fc3_b = (const float*)d_in[17];
        src   = (const int*)d_in[18];
        dst   = (const int*)d_in[19];
        etype = (const int*)d_in[20];
        n2g   = (const int*)d_in[21];
    }
    float* out = (float*)d_out;

    const dim3 gemm_grid(NR, (NN + 127) / 128);          // relation fastest -> A L2 reuse
    const dim3 splitw_grid(64, NR);
    const int split_blocks = (NN * 32 + 255) / 256;      // 6250
    const int node_warp_blocks = NN / 8;                 // 6250
    const int edge_blocks = (NE + 255) / 256;            // 2344
    const int node_blocks = (NN + 255) / 256;            // 196
    const int gemm_smem = 3 * STAGE_FULL;                // 110592 B

    static int smem_set = 0;
    if (!smem_set) {
        cudaFuncSetAttribute(k_gemm_mma, cudaFuncAttributeMaxDynamicSharedMemorySize, gemm_smem);
        smem_set = 1;
    }

    // ---- layer 1 front half; GEMM is launch #4 for ncu capture
    k_splitw<<<splitw_grid, 256>>>(bases1, comp1);       // 1
    k_split<<<split_blocks, 256>>>(features);            // 2
    k_hist0<<<node_blocks, 256>>>();                     // 3
    k_gemm_mma<<<gemm_grid, 256, gemm_smem>>>();         // 4  <- profiled
    // ---- CSR build (needed only before first gather)
    k_hist<<<edge_blocks, 256>>>(dst);                   // 5
    k_scan<<<1, 1024>>>();                               // 6
    k_fill<<<edge_blocks, 256>>>(src, dst, etype);       // 7
    // ---- layer 1 -> A2 (fused gather+relu+split)
    k_gather_split<<<node_warp_blocks, 256>>>(bias1);    // 8
    // ---- layer 2
    k_splitw<<<splitw_grid, 256>>>(bases2, comp2);
    k_gemm_mma<<<gemm_grid, 256, gemm_smem>>>();
    k_gather_split<<<node_warp_blocks, 256>>>(bias2);
    // ---- layer 3
    k_splitw<<<splitw_grid, 256>>>(bases3, comp3);
    k_gemm_mma<<<gemm_grid, 256, gemm_smem>>>();
    k_gather<<<node_warp_blocks, 256>>>(bias3);
    // ---- attention pooling on g_hA
    k_poolinit<<<(NG * DIM + 255) / 256, 256>>>();
    k_gate<<<node_warp_blocks, 256>>>(gate_w, gate_b, n2g);
    k_expsum<<<(NN + 255) / 256, 256>>>(n2g);
    k_readout<<<node_warp_blocks, 256>>>(n2g);
    // ---- MLP head
    k_mlp<<<NG, DIM>>>(fc1_w, fc1_b, fc2_w, fc2_b, fc3_w, fc3_b, out);
}